// round 1
// baseline (speedup 1.0000x reference)
#include <cuda_runtime.h>
#include <cuda_bf16.h>
#include <math.h>

#define TOT   16384
#define NPTS  4096
#define BATCH 4
#define KNN   16
#define HD    128
#define IND   64
#define APITCH 132   // padded pitch for transposed smem buffer (float4-aligned)

// ---------------- device scratch (static, allocation-rule compliant) -------------
__device__ int   g_idx[TOT * KNN];
__device__ float g_t  [TOT * HD];
__device__ float g_q  [TOT * HD];
__device__ float g_kf [TOT * HD];
__device__ float g_v  [TOT * HD];
__device__ float g_agg[TOT * HD];
__device__ float g_part[128 * 2 * HD];
__device__ float g_stats[2 * HD];

// ============================ ball query =========================================
// For each query point: K smallest indices j with ||xyz_i - xyz_j||^2 <= 100,
// padded with the first qualifying index. Exact integer arithmetic (coords < 100).
__global__ __launch_bounds__(128) void ball_kernel(const int* __restrict__ coords) {
    __shared__ int sP[NPTS];
    int b = (blockIdx.x * 128) / NPTS;
    int base = b * NPTS;
    for (int j = threadIdx.x; j < NPTS; j += 128) {
        int4 c = *(const int4*)&coords[(size_t)(base + j) * 4];
        sP[j] = c.y | (c.z << 8) | (c.w << 16);
    }
    __syncthreads();
    int qi = blockIdx.x * 128 + threadIdx.x;
    int me = sP[qi - base];
    int qx = me & 255, qy = (me >> 8) & 255, qz = me >> 16;
    int cnt = 0, first = 0;
    int* out = g_idx + (size_t)qi * KNN;
    #pragma unroll 8
    for (int j = 0; j < NPTS; j++) {
        int p = sP[j];
        int dx = qx - (p & 255);
        int dy = qy - ((p >> 8) & 255);
        int dz = qz - (p >> 16);
        int d2 = dx * dx + dy * dy + dz * dz;
        if (d2 <= 100 && cnt < KNN) {
            int gj = base + j;
            out[cnt] = gj;
            if (cnt == 0) first = gj;
            cnt++;
        }
    }
    for (int k = cnt; k < KNN; k++) out[k] = first;
}

// ============================ GEMM: t = x @ W_top + b_top  (16384x64x128) ========
__global__ __launch_bounds__(256) void topproj_kernel(const float* __restrict__ x,
                                                      const float* __restrict__ W,
                                                      const float* __restrict__ bias) {
    __shared__ float As[16][128];
    __shared__ float Bs[16][128];
    int tid = threadIdx.x;
    int ty = tid >> 4, tx = tid & 15;
    int row0 = blockIdx.x * 128;
    float acc[8][8] = {};
    for (int kt = 0; kt < 64; kt += 16) {
        for (int e = tid; e < 512; e += 256) {
            int r = e >> 2, s = e & 3;
            float4 v = *(const float4*)&x[(size_t)(row0 + r) * 64 + kt + s * 4];
            As[s * 4 + 0][r] = v.x; As[s * 4 + 1][r] = v.y;
            As[s * 4 + 2][r] = v.z; As[s * 4 + 3][r] = v.w;
        }
        for (int e = tid; e < 512; e += 256) {
            int k = e >> 5, s = e & 31;
            *(float4*)&Bs[k][s * 4] = *(const float4*)&W[(size_t)(kt + k) * 128 + s * 4];
        }
        __syncthreads();
        #pragma unroll
        for (int k = 0; k < 16; k++) {
            float4 a0 = *(const float4*)&As[k][ty * 8];
            float4 a1 = *(const float4*)&As[k][ty * 8 + 4];
            float4 b0 = *(const float4*)&Bs[k][tx * 8];
            float4 b1 = *(const float4*)&Bs[k][tx * 8 + 4];
            float av[8] = {a0.x, a0.y, a0.z, a0.w, a1.x, a1.y, a1.z, a1.w};
            float bv[8] = {b0.x, b0.y, b0.z, b0.w, b1.x, b1.y, b1.z, b1.w};
            #pragma unroll
            for (int i = 0; i < 8; i++)
                #pragma unroll
                for (int j = 0; j < 8; j++)
                    acc[i][j] += av[i] * bv[j];
        }
        __syncthreads();
    }
    #pragma unroll
    for (int i = 0; i < 8; i++)
        #pragma unroll
        for (int j = 0; j < 8; j++)
            g_t[(size_t)(row0 + ty * 8 + i) * 128 + tx * 8 + j] =
                acc[i][j] + __ldg(&bias[tx * 8 + j]);
}

// ============================ BN partial / finalize ==============================
template <int C>
__global__ __launch_bounds__(256) void bn_partial_k(const float* __restrict__ src) {
    constexpr int SUB = 256 / C;
    int c = threadIdx.x % C, sub = threadIdx.x / C;
    int row0 = blockIdx.x * 128;
    float s = 0.f, ss = 0.f;
    for (int r = sub; r < 128; r += SUB) {
        float v = src[(size_t)(row0 + r) * C + c];
        s += v; ss += v * v;
    }
    __shared__ float red[2][256];
    red[0][threadIdx.x] = s; red[1][threadIdx.x] = ss;
    __syncthreads();
    if (sub == 0) {
        for (int u = 1; u < SUB; u++) { s += red[0][u * C + c]; ss += red[1][u * C + c]; }
        g_part[blockIdx.x * 2 * C + c]     = s;
        g_part[blockIdx.x * 2 * C + C + c] = ss;
    }
}

template <int C>
__global__ void bn_finalize_k() {
    int c = threadIdx.x;
    float s = 0.f, ss = 0.f;
    for (int b = 0; b < 128; b++) {
        s  += g_part[b * 2 * C + c];
        ss += g_part[b * 2 * C + C + c];
    }
    float m = s / (float)TOT;
    float var = ss / (float)TOT - m * m;
    g_stats[c]     = m;
    g_stats[C + c] = rsqrtf(var + 1e-5f);
}

// ============== q,kf,v = normalize(t) @ {W_phi,W_psi,W_alpha}  (16384x128x128) ===
__global__ __launch_bounds__(256) void qkv_kernel(const float* __restrict__ g1v,
                                                  const float* __restrict__ be1,
                                                  const float* __restrict__ Wphi,
                                                  const float* __restrict__ Wpsi,
                                                  const float* __restrict__ Walpha) {
    __shared__ float As[16][128];
    __shared__ float Bs[16][128];
    __shared__ float sScale[128], sShift[128];
    int tid = threadIdx.x;
    const float* W = (blockIdx.y == 0) ? Wphi : (blockIdx.y == 1) ? Wpsi : Walpha;
    float* out = (blockIdx.y == 0) ? g_q : (blockIdx.y == 1) ? g_kf : g_v;
    if (tid < 128) {
        float m = g_stats[tid], is = g_stats[128 + tid];
        float sc = is * g1v[tid];
        sScale[tid] = sc;
        sShift[tid] = be1[tid] - m * sc;
    }
    __syncthreads();
    int ty = tid >> 4, tx = tid & 15;
    int row0 = blockIdx.x * 128;
    float acc[8][8] = {};
    for (int kt = 0; kt < 128; kt += 16) {
        for (int e = tid; e < 512; e += 256) {
            int r = e >> 2, s = e & 3;
            float4 v = *(const float4*)&g_t[(size_t)(row0 + r) * 128 + kt + s * 4];
            int k0 = s * 4;
            As[k0 + 0][r] = v.x * sScale[kt + k0 + 0] + sShift[kt + k0 + 0];
            As[k0 + 1][r] = v.y * sScale[kt + k0 + 1] + sShift[kt + k0 + 1];
            As[k0 + 2][r] = v.z * sScale[kt + k0 + 2] + sShift[kt + k0 + 2];
            As[k0 + 3][r] = v.w * sScale[kt + k0 + 3] + sShift[kt + k0 + 3];
        }
        for (int e = tid; e < 512; e += 256) {
            int k = e >> 5, s = e & 31;
            *(float4*)&Bs[k][s * 4] = *(const float4*)&W[(size_t)(kt + k) * 128 + s * 4];
        }
        __syncthreads();
        #pragma unroll
        for (int k = 0; k < 16; k++) {
            float4 a0 = *(const float4*)&As[k][ty * 8];
            float4 a1 = *(const float4*)&As[k][ty * 8 + 4];
            float4 b0 = *(const float4*)&Bs[k][tx * 8];
            float4 b1 = *(const float4*)&Bs[k][tx * 8 + 4];
            float av[8] = {a0.x, a0.y, a0.z, a0.w, a1.x, a1.y, a1.z, a1.w};
            float bv[8] = {b0.x, b0.y, b0.z, b0.w, b1.x, b1.y, b1.z, b1.w};
            #pragma unroll
            for (int i = 0; i < 8; i++)
                #pragma unroll
                for (int j = 0; j < 8; j++)
                    acc[i][j] += av[i] * bv[j];
        }
        __syncthreads();
    }
    #pragma unroll
    for (int i = 0; i < 8; i++)
        #pragma unroll
        for (int j = 0; j < 8; j++)
            out[(size_t)(row0 + ty * 8 + i) * 128 + tx * 8 + j] = acc[i][j];
}

// ============================ fused per-point attention ==========================
// 8 points/block, 128 rows (point,knn) x 128 channels per stage, everything in smem.
__device__ __forceinline__ void mm128(const float* __restrict__ A, const float* __restrict__ B,
                                      float acc[8][8], int rr0, int cc0) {
    #pragma unroll 2
    for (int k = 0; k < 128; k++) {
        float4 a0 = *(const float4*)(A + k * APITCH + rr0);
        float4 a1 = *(const float4*)(A + k * APITCH + rr0 + 4);
        float4 b0 = *(const float4*)(B + k * 128 + cc0);
        float4 b1 = *(const float4*)(B + k * 128 + cc0 + 4);
        float av[8] = {a0.x, a0.y, a0.z, a0.w, a1.x, a1.y, a1.z, a1.w};
        float bv[8] = {b0.x, b0.y, b0.z, b0.w, b1.x, b1.y, b1.z, b1.w};
        #pragma unroll
        for (int i = 0; i < 8; i++)
            #pragma unroll
            for (int j = 0; j < 8; j++)
                acc[i][j] += av[i] * bv[j];
    }
}

__global__ __launch_bounds__(256) void fused_kernel(const int* __restrict__ coords,
                                                    const float* __restrict__ Wd1,
                                                    const float* __restrict__ bd1,
                                                    const float* __restrict__ Wd2,
                                                    const float* __restrict__ bd2,
                                                    const float* __restrict__ Wg1,
                                                    const float* __restrict__ bg1,
                                                    const float* __restrict__ Wg2,
                                                    const float* __restrict__ bg2) {
    extern __shared__ float sm[];
    float* BufA = sm;                       // [128][APITCH] transposed intermediates / logits
    float* BufB = BufA + 128 * APITCH;      // [128][128] delta
    float* BufC = BufB + 128 * 128;         // [128][128] weights, then gathered v
    float* sQ   = BufC + 128 * 128;         // [8][128]
    float* sRel = sQ + 8 * 128;             // [128][3]
    float* sWd1 = sRel + 128 * 3;           // [3][128]
    float* sBd1 = sWd1 + 384;               // [128]
    int*   sIdx = (int*)(sBd1 + 128);       // [128]

    int tid = threadIdx.x;
    int p0 = blockIdx.x * 8;

    if (tid < 128) {
        sIdx[tid] = g_idx[(size_t)p0 * KNN + tid];
        sBd1[tid] = bd1[tid];
    }
    for (int e = tid; e < 384; e += 256) sWd1[e] = Wd1[e];
    {
        int pp = tid >> 5, s = tid & 31;
        *(float4*)&sQ[pp * 128 + s * 4] = *(const float4*)&g_q[(size_t)(p0 + pp) * 128 + s * 4];
    }
    __syncthreads();

    // relative positions + load Wd2
    if (tid < 128) {
        int i = p0 + (tid >> 4);
        int j = sIdx[tid];
        int4 ci = *(const int4*)&coords[(size_t)i * 4];
        int4 cj = *(const int4*)&coords[(size_t)j * 4];
        sRel[tid * 3 + 0] = (float)(ci.y - cj.y);
        sRel[tid * 3 + 1] = (float)(ci.z - cj.z);
        sRel[tid * 3 + 2] = (float)(ci.w - cj.w);
    }
    for (int e = tid; e < 4096; e += 256) {
        int k = e >> 5, s = e & 31;
        *(float4*)&BufC[k * 128 + s * 4] = *(const float4*)&Wd2[(size_t)k * 128 + s * 4];
    }
    __syncthreads();

    // stage 1: h1^T = relu(rel @ Wd1 + bd1)^T -> BufA[k][r]
    for (int e = tid; e < 128 * 128; e += 256) {
        int r = e >> 7, c = e & 127;
        float v = sBd1[c] + sRel[r * 3] * sWd1[c] + sRel[r * 3 + 1] * sWd1[128 + c]
                + sRel[r * 3 + 2] * sWd1[256 + c];
        BufA[c * APITCH + r] = fmaxf(v, 0.f);
    }
    __syncthreads();

    int ty = tid >> 4, tx = tid & 15;
    int rr0 = ty * 8, cc0 = tx * 8;
    float acc[8][8];

    // GEMM1: delta = h1 @ Wd2 + bd2
    #pragma unroll
    for (int i = 0; i < 8; i++)
        #pragma unroll
        for (int j = 0; j < 8; j++) acc[i][j] = 0.f;
    mm128(BufA, BufC, acc, rr0, cc0);
    __syncthreads();

    // epilogue1: BufB <- delta, BufA <- (q - kf[g] + delta)^T ; load Wg1
    {
        float bj[8];
        #pragma unroll
        for (int j = 0; j < 8; j++) bj[j] = __ldg(&bd2[cc0 + j]);
        #pragma unroll
        for (int i = 0; i < 8; i++) {
            int r = rr0 + i;
            int pl = r >> 4;
            int gi = sIdx[r];
            const float* kfr = g_kf + (size_t)gi * 128 + cc0;
            float4 k0 = *(const float4*)(kfr);
            float4 k1 = *(const float4*)(kfr + 4);
            float kv[8] = {k0.x, k0.y, k0.z, k0.w, k1.x, k1.y, k1.z, k1.w};
            #pragma unroll
            for (int j = 0; j < 8; j++) {
                float delta = acc[i][j] + bj[j];
                BufB[r * 128 + cc0 + j] = delta;
                BufA[(cc0 + j) * APITCH + r] = sQ[pl * 128 + cc0 + j] - kv[j] + delta;
            }
        }
    }
    for (int e = tid; e < 4096; e += 256) {
        int k = e >> 5, s = e & 31;
        *(float4*)&BufC[k * 128 + s * 4] = *(const float4*)&Wg1[(size_t)k * 128 + s * 4];
    }
    __syncthreads();

    // GEMM2: h2 = relu(apre @ Wg1 + bg1)
    #pragma unroll
    for (int i = 0; i < 8; i++)
        #pragma unroll
        for (int j = 0; j < 8; j++) acc[i][j] = 0.f;
    mm128(BufA, BufC, acc, rr0, cc0);
    __syncthreads();

    {
        float bj[8];
        #pragma unroll
        for (int j = 0; j < 8; j++) bj[j] = __ldg(&bg1[cc0 + j]);
        #pragma unroll
        for (int i = 0; i < 8; i++) {
            int r = rr0 + i;
            #pragma unroll
            for (int j = 0; j < 8; j++)
                BufA[(cc0 + j) * APITCH + r] = fmaxf(acc[i][j] + bj[j], 0.f);
        }
    }
    for (int e = tid; e < 4096; e += 256) {
        int k = e >> 5, s = e & 31;
        *(float4*)&BufC[k * 128 + s * 4] = *(const float4*)&Wg2[(size_t)k * 128 + s * 4];
    }
    __syncthreads();

    // GEMM3: a = h2 @ Wg2 + bg2
    #pragma unroll
    for (int i = 0; i < 8; i++)
        #pragma unroll
        for (int j = 0; j < 8; j++) acc[i][j] = 0.f;
    mm128(BufA, BufC, acc, rr0, cc0);
    __syncthreads();

    // epilogue3: BufA <- a (row-major), BufC <- gathered v
    {
        float bj[8];
        #pragma unroll
        for (int j = 0; j < 8; j++) bj[j] = __ldg(&bg2[cc0 + j]);
        #pragma unroll
        for (int i = 0; i < 8; i++) {
            int r = rr0 + i;
            #pragma unroll
            for (int j = 0; j < 8; j++)
                BufA[r * APITCH + cc0 + j] = acc[i][j] + bj[j];
        }
    }
    for (int e = tid; e < 4096; e += 256) {
        int r = e >> 5, s = e & 31;
        *(float4*)&BufC[r * 128 + s * 4] =
            *(const float4*)&g_v[(size_t)sIdx[r] * 128 + s * 4];
    }
    __syncthreads();

    // softmax over K per (point, channel) + aggregate
    for (int t = tid; t < 8 * 128; t += 256) {
        int pl = t >> 7, c = t & 127;
        int rb = pl * 16;
        float m = -1e30f;
        #pragma unroll
        for (int k = 0; k < 16; k++)
            m = fmaxf(m, BufA[(rb + k) * APITCH + c]);
        float s = 0.f, a2 = 0.f;
        #pragma unroll
        for (int k = 0; k < 16; k++) {
            int r = rb + k;
            float e2 = __expf(BufA[r * APITCH + c] - m);
            s += e2;
            a2 += e2 * (BufC[r * 128 + c] + BufB[r * 128 + c]);
        }
        g_agg[(size_t)(p0 + pl) * 128 + c] = a2 / s;
    }
}

// ============================ down-proj: agg @ W_down + b_down (16384x128x64) ====
__global__ __launch_bounds__(256) void down_kernel(const float* __restrict__ W,
                                                   const float* __restrict__ bias,
                                                   float* __restrict__ out) {
    __shared__ float As[16][128];
    __shared__ float Bs[16][64];
    int tid = threadIdx.x;
    int ty = tid >> 4, tx = tid & 15;
    int row0 = blockIdx.x * 128;
    float acc[8][4] = {};
    for (int kt = 0; kt < 128; kt += 16) {
        for (int e = tid; e < 512; e += 256) {
            int r = e >> 2, s = e & 3;
            float4 v = *(const float4*)&g_agg[(size_t)(row0 + r) * 128 + kt + s * 4];
            As[s * 4 + 0][r] = v.x; As[s * 4 + 1][r] = v.y;
            As[s * 4 + 2][r] = v.z; As[s * 4 + 3][r] = v.w;
        }
        if (tid < 256) {
            int k = tid >> 4, s = tid & 15;
            *(float4*)&Bs[k][s * 4] = *(const float4*)&W[(size_t)(kt + k) * 64 + s * 4];
        }
        __syncthreads();
        #pragma unroll
        for (int k = 0; k < 16; k++) {
            float4 a0 = *(const float4*)&As[k][ty * 8];
            float4 a1 = *(const float4*)&As[k][ty * 8 + 4];
            float4 b = *(const float4*)&Bs[k][tx * 4];
            float av[8] = {a0.x, a0.y, a0.z, a0.w, a1.x, a1.y, a1.z, a1.w};
            float bv[4] = {b.x, b.y, b.z, b.w};
            #pragma unroll
            for (int i = 0; i < 8; i++)
                #pragma unroll
                for (int j = 0; j < 4; j++)
                    acc[i][j] += av[i] * bv[j];
        }
        __syncthreads();
    }
    #pragma unroll
    for (int i = 0; i < 8; i++)
        #pragma unroll
        for (int j = 0; j < 4; j++)
            out[(size_t)(row0 + ty * 8 + i) * 64 + tx * 4 + j] =
                acc[i][j] + __ldg(&bias[tx * 4 + j]);
}

// ============================ final BN + residual ================================
__global__ __launch_bounds__(256) void final_kernel(const float* __restrict__ x,
                                                    const float* __restrict__ g2,
                                                    const float* __restrict__ be2,
                                                    float* __restrict__ out) {
    int e = blockIdx.x * 256 + threadIdx.x;
    if (e < TOT * IND) {
        int c = e & 63;
        float m = g_stats[c], is = g_stats[IND + c];
        out[e] = (out[e] - m) * is * g2[c] + be2[c] + x[e];
    }
}

// ============================ launch =============================================
extern "C" void kernel_launch(void* const* d_in, const int* in_sizes, int n_in,
                              void* d_out, int out_size) {
    const int*   coords  = (const int*)  d_in[0];
    const float* x       = (const float*)d_in[1];
    const float* W_top   = (const float*)d_in[2];
    const float* b_top   = (const float*)d_in[3];
    const float* g1      = (const float*)d_in[4];
    const float* be1     = (const float*)d_in[5];
    const float* W_phi   = (const float*)d_in[6];
    const float* W_psi   = (const float*)d_in[7];
    const float* W_alpha = (const float*)d_in[8];
    const float* Wd1     = (const float*)d_in[9];
    const float* bd1     = (const float*)d_in[10];
    const float* Wd2     = (const float*)d_in[11];
    const float* bd2     = (const float*)d_in[12];
    const float* Wg1     = (const float*)d_in[13];
    const float* bg1     = (const float*)d_in[14];
    const float* Wg2     = (const float*)d_in[15];
    const float* bg2     = (const float*)d_in[16];
    const float* W_down  = (const float*)d_in[17];
    const float* b_down  = (const float*)d_in[18];
    const float* g2      = (const float*)d_in[19];
    const float* be2     = (const float*)d_in[20];
    float* out = (float*)d_out;

    const size_t SMEM_D = (size_t)(128 * APITCH + 128 * 128 * 2 + 8 * 128 + 128 * 3
                                   + 384 + 128 + 128) * 4;
    cudaFuncSetAttribute(fused_kernel, cudaFuncAttributeMaxDynamicSharedMemorySize,
                         (int)SMEM_D);

    void* p_t = nullptr;
    cudaGetSymbolAddress(&p_t, g_t);

    ball_kernel<<<TOT / 128, 128>>>(coords);
    topproj_kernel<<<TOT / 128, 256>>>(x, W_top, b_top);
    bn_partial_k<128><<<128, 256>>>((const float*)p_t);
    bn_finalize_k<128><<<1, 128>>>();
    qkv_kernel<<<dim3(TOT / 128, 3), 256>>>(g1, be1, W_phi, W_psi, W_alpha);
    fused_kernel<<<TOT / 8, 256, SMEM_D>>>(coords, Wd1, bd1, Wd2, bd2,
                                           Wg1, bg1, Wg2, bg2);
    down_kernel<<<TOT / 128, 256>>>(W_down, b_down, out);
    bn_partial_k<64><<<128, 256>>>((const float*)out);
    bn_finalize_k<64><<<1, 64>>>();
    final_kernel<<<(TOT * IND + 255) / 256, 256>>>(x, g2, be2, out);
}

// round 4
// speedup vs baseline: 1.7751x; 1.7751x over previous
#include <cuda_runtime.h>
#include <cuda_bf16.h>
#include <cstdint>
#include <math.h>

#define TOT   16384
#define NPTS  4096
#define KNN   16
#define HD    128
#define IND   64
#define APITCH 132   // A/D buffers: bank = 4*row + col  -> conflict-free A frags
#define WPITCH 136   // W buffer:    bank = 8*row + col  -> conflict-free B frags

// ---------------- device scratch ------------------------------------------------
__device__ int   g_idx[TOT * KNN];
__device__ float g_t  [TOT * HD];
__device__ float g_q  [TOT * HD];
__device__ float g_kf [TOT * HD];
__device__ float g_v  [TOT * HD];
__device__ float g_agg[TOT * HD];
__device__ float g_part[128 * 2 * HD];
__device__ float g_stats[2 * HD];

__device__ __forceinline__ float to_tf32(float x) {
    unsigned int r;
    asm("cvt.rna.tf32.f32 %0, %1;" : "=r"(r) : "f"(x));
    return __uint_as_float(r);
}

// ============================ ball query =========================================
__global__ __launch_bounds__(128) void ball_kernel(const int* __restrict__ coords) {
    __shared__ int sP[NPTS];
    int b = (blockIdx.x * 128) / NPTS;
    int base = b * NPTS;
    for (int j = threadIdx.x; j < NPTS; j += 128) {
        int4 c = *(const int4*)&coords[(size_t)(base + j) * 4];
        sP[j] = c.y | (c.z << 8) | (c.w << 16);
    }
    __syncthreads();
    int qi = blockIdx.x * 128 + threadIdx.x;
    int me = sP[qi - base];
    int qx = me & 255, qy = (me >> 8) & 255, qz = me >> 16;
    int cnt = 0, first = 0;
    int* out = g_idx + (size_t)qi * KNN;
    #pragma unroll 8
    for (int j = 0; j < NPTS; j++) {
        int p = sP[j];
        int dx = qx - (p & 255);
        int dy = qy - ((p >> 8) & 255);
        int dz = qz - (p >> 16);
        int d2 = dx * dx + dy * dy + dz * dz;
        if (d2 <= 100 && cnt < KNN) {
            int gj = base + j;
            out[cnt] = gj;
            if (cnt == 0) first = gj;
            cnt++;
        }
    }
    for (int k = cnt; k < KNN; k++) out[k] = first;
}

// ============================ GEMM: t = x @ W_top + b_top  (16384x64x128) ========
__global__ __launch_bounds__(256) void topproj_kernel(const float* __restrict__ x,
                                                      const float* __restrict__ W,
                                                      const float* __restrict__ bias) {
    __shared__ float As[16][128];
    __shared__ float Bs[16][128];
    int tid = threadIdx.x;
    int ty = tid >> 4, tx = tid & 15;
    int row0 = blockIdx.x * 128;
    float acc[8][8] = {};
    for (int kt = 0; kt < 64; kt += 16) {
        for (int e = tid; e < 512; e += 256) {
            int r = e >> 2, s = e & 3;
            float4 v = *(const float4*)&x[(size_t)(row0 + r) * 64 + kt + s * 4];
            As[s * 4 + 0][r] = v.x; As[s * 4 + 1][r] = v.y;
            As[s * 4 + 2][r] = v.z; As[s * 4 + 3][r] = v.w;
        }
        for (int e = tid; e < 512; e += 256) {
            int k = e >> 5, s = e & 31;
            *(float4*)&Bs[k][s * 4] = *(const float4*)&W[(size_t)(kt + k) * 128 + s * 4];
        }
        __syncthreads();
        #pragma unroll
        for (int k = 0; k < 16; k++) {
            float4 a0 = *(const float4*)&As[k][ty * 8];
            float4 a1 = *(const float4*)&As[k][ty * 8 + 4];
            float4 b0 = *(const float4*)&Bs[k][tx * 8];
            float4 b1 = *(const float4*)&Bs[k][tx * 8 + 4];
            float av[8] = {a0.x, a0.y, a0.z, a0.w, a1.x, a1.y, a1.z, a1.w};
            float bv[8] = {b0.x, b0.y, b0.z, b0.w, b1.x, b1.y, b1.z, b1.w};
            #pragma unroll
            for (int i = 0; i < 8; i++)
                #pragma unroll
                for (int j = 0; j < 8; j++)
                    acc[i][j] += av[i] * bv[j];
        }
        __syncthreads();
    }
    #pragma unroll
    for (int i = 0; i < 8; i++)
        #pragma unroll
        for (int j = 0; j < 8; j++)
            g_t[(size_t)(row0 + ty * 8 + i) * 128 + tx * 8 + j] =
                acc[i][j] + __ldg(&bias[tx * 8 + j]);
}

// ============================ BN partial / finalize ==============================
template <int C>
__global__ __launch_bounds__(256) void bn_partial_k(const float* __restrict__ src) {
    constexpr int SUB = 256 / C;
    int c = threadIdx.x % C, sub = threadIdx.x / C;
    int row0 = blockIdx.x * 128;
    float s = 0.f, ss = 0.f;
    for (int r = sub; r < 128; r += SUB) {
        float v = src[(size_t)(row0 + r) * C + c];
        s += v; ss += v * v;
    }
    __shared__ float red[2][256];
    red[0][threadIdx.x] = s; red[1][threadIdx.x] = ss;
    __syncthreads();
    if (sub == 0) {
        for (int u = 1; u < SUB; u++) { s += red[0][u * C + c]; ss += red[1][u * C + c]; }
        g_part[blockIdx.x * 2 * C + c]     = s;
        g_part[blockIdx.x * 2 * C + C + c] = ss;
    }
}

template <int C>
__global__ __launch_bounds__(256) void bn_finalize_k() {
    constexpr int NSUB = 256 / C;
    int c = threadIdx.x % C, sub = threadIdx.x / C;
    float s = 0.f, ss = 0.f;
    #pragma unroll 4
    for (int b = sub; b < 128; b += NSUB) {
        s  += g_part[b * 2 * C + c];
        ss += g_part[b * 2 * C + C + c];
    }
    __shared__ float red[2][256];
    red[0][threadIdx.x] = s; red[1][threadIdx.x] = ss;
    __syncthreads();
    if (sub == 0) {
        #pragma unroll
        for (int u = 1; u < NSUB; u++) { s += red[0][u * C + c]; ss += red[1][u * C + c]; }
        float m = s / (float)TOT;
        float var = ss / (float)TOT - m * m;
        g_stats[c]     = m;
        g_stats[C + c] = rsqrtf(var + 1e-5f);
    }
}

// ============================ tf32 mma GEMM core =================================
// 128x128x128; 8 warps; warp tile 64x32 (wr=wid>>2, wc=wid&3); m16n8k8 tf32.
// A [128][APITCH] row-major tf32; W [128][WPITCH] k-major tf32.
__device__ __forceinline__ void gemm128_mma(const float* __restrict__ A,
                                            const float* __restrict__ W,
                                            float acc[4][4][4],
                                            int wr, int wc, int g, int t) {
    #pragma unroll
    for (int i = 0; i < 4; i++)
        #pragma unroll
        for (int j = 0; j < 4; j++)
            #pragma unroll
            for (int r = 0; r < 4; r++) acc[i][j][r] = 0.f;
    #pragma unroll 4
    for (int kk = 0; kk < 16; kk++) {
        const int k0 = kk * 8;
        unsigned int a[4][4];
        #pragma unroll
        for (int mi = 0; mi < 4; mi++) {
            const float* ap = A + (size_t)(wr * 64 + mi * 16 + g) * APITCH + k0 + t;
            a[mi][0] = __float_as_uint(ap[0]);
            a[mi][1] = __float_as_uint(ap[8 * APITCH]);
            a[mi][2] = __float_as_uint(ap[4]);
            a[mi][3] = __float_as_uint(ap[8 * APITCH + 4]);
        }
        #pragma unroll
        for (int ni = 0; ni < 4; ni++) {
            const float* bp = W + (size_t)(k0 + t) * WPITCH + wc * 32 + ni * 8 + g;
            unsigned int b0 = __float_as_uint(bp[0]);
            unsigned int b1 = __float_as_uint(bp[4 * WPITCH]);
            #pragma unroll
            for (int mi = 0; mi < 4; mi++) {
                asm volatile(
                    "mma.sync.aligned.m16n8k8.row.col.f32.tf32.tf32.f32 "
                    "{%0,%1,%2,%3}, {%4,%5,%6,%7}, {%8,%9}, {%0,%1,%2,%3};\n"
                    : "+f"(acc[mi][ni][0]), "+f"(acc[mi][ni][1]),
                      "+f"(acc[mi][ni][2]), "+f"(acc[mi][ni][3])
                    : "r"(a[mi][0]), "r"(a[mi][1]), "r"(a[mi][2]), "r"(a[mi][3]),
                      "r"(b0), "r"(b1));
            }
        }
    }
}

// ============== q,kf,v = normalize(t) @ {W_phi,W_psi,W_alpha} (mma tf32) =========
__global__ __launch_bounds__(256) void qkv_kernel(const float* __restrict__ g1v,
                                                  const float* __restrict__ be1,
                                                  const float* __restrict__ Wphi,
                                                  const float* __restrict__ Wpsi,
                                                  const float* __restrict__ Walpha) {
    extern __shared__ float sm[];
    float* BufA = sm;                    // [128][APITCH]
    float* BufW = BufA + 128 * APITCH;   // [128][WPITCH]
    __shared__ float sScale[128], sShift[128];
    int tid = threadIdx.x;
    const float* W = (blockIdx.y == 0) ? Wphi : (blockIdx.y == 1) ? Wpsi : Walpha;
    float* out = (blockIdx.y == 0) ? g_q : (blockIdx.y == 1) ? g_kf : g_v;
    if (tid < 128) {
        float m = g_stats[tid], is = g_stats[128 + tid];
        float sc = is * g1v[tid];
        sScale[tid] = sc;
        sShift[tid] = be1[tid] - m * sc;
    }
    __syncthreads();
    int row0 = blockIdx.x * 128;
    // A = tf32(BN(t)), W = tf32(W)
    for (int e = tid; e < 4096; e += 256) {
        int r = e >> 5, s = (e & 31) * 4;
        float4 v = *(const float4*)&g_t[(size_t)(row0 + r) * 128 + s];
        float4 o;
        o.x = to_tf32(v.x * sScale[s] + sShift[s]);
        o.y = to_tf32(v.y * sScale[s + 1] + sShift[s + 1]);
        o.z = to_tf32(v.z * sScale[s + 2] + sShift[s + 2]);
        o.w = to_tf32(v.w * sScale[s + 3] + sShift[s + 3]);
        *(float4*)&BufA[r * APITCH + s] = o;
    }
    for (int e = tid; e < 4096; e += 256) {
        int k = e >> 5, s = (e & 31) * 4;
        float4 v = *(const float4*)&W[(size_t)k * 128 + s];
        float4 o = {to_tf32(v.x), to_tf32(v.y), to_tf32(v.z), to_tf32(v.w)};
        *(float4*)&BufW[k * WPITCH + s] = o;
    }
    __syncthreads();

    int wid = tid >> 5, lane = tid & 31;
    int wr = wid >> 2, wc = wid & 3;
    int g = lane >> 2, t = lane & 3;
    float acc[4][4][4];
    gemm128_mma(BufA, BufW, acc, wr, wc, g, t);

    #pragma unroll
    for (int mi = 0; mi < 4; mi++) {
        int r0 = row0 + wr * 64 + mi * 16 + g;
        #pragma unroll
        for (int ni = 0; ni < 4; ni++) {
            int c0 = wc * 32 + ni * 8 + 2 * t;
            *(float2*)&out[(size_t)r0 * 128 + c0] =
                make_float2(acc[mi][ni][0], acc[mi][ni][1]);
            *(float2*)&out[(size_t)(r0 + 8) * 128 + c0] =
                make_float2(acc[mi][ni][2], acc[mi][ni][3]);
        }
    }
}

// ============================ fused per-point attention (mma tf32) ==============
__global__ __launch_bounds__(256) void fused_kernel(const int* __restrict__ coords,
                                                    const float* __restrict__ Wd1,
                                                    const float* __restrict__ bd1,
                                                    const float* __restrict__ Wd2,
                                                    const float* __restrict__ bd2,
                                                    const float* __restrict__ Wg1,
                                                    const float* __restrict__ bg1,
                                                    const float* __restrict__ Wg2,
                                                    const float* __restrict__ bg2) {
    extern __shared__ float sm[];
    float* BufA = sm;                      // [128][APITCH] mma A operand / logits
    float* BufW = BufA + 128 * APITCH;     // [128][WPITCH] weights, then gathered v
    float* BufD = BufW + 128 * WPITCH;     // [128][APITCH] delta
    float* sQ   = BufD + 128 * APITCH;     // [8][128]
    float* sRel = sQ + 8 * 128;            // [128][3]
    float* sWd1 = sRel + 128 * 3;          // [3][128]
    float* sBd1 = sWd1 + 384;              // [128]
    int*   sIdx = (int*)(sBd1 + 128);      // [128]

    int tid = threadIdx.x;
    int p0 = blockIdx.x * 8;
    int wid = tid >> 5, lane = tid & 31;
    int wr = wid >> 2, wc = wid & 3;
    int g = lane >> 2, t = lane & 3;

    if (tid < 128) {
        sIdx[tid] = g_idx[(size_t)p0 * KNN + tid];
        sBd1[tid] = bd1[tid];
    }
    for (int e = tid; e < 384; e += 256) sWd1[e] = Wd1[e];
    {
        int pp = tid >> 5, s = (tid & 31) * 4;
        *(float4*)&sQ[pp * 128 + s] = *(const float4*)&g_q[(size_t)(p0 + pp) * 128 + s];
    }
    __syncthreads();

    if (tid < 128) {
        int i = p0 + (tid >> 4);
        int j = sIdx[tid];
        int4 ci = *(const int4*)&coords[(size_t)i * 4];
        int4 cj = *(const int4*)&coords[(size_t)j * 4];
        sRel[tid * 3 + 0] = (float)(ci.y - cj.y);
        sRel[tid * 3 + 1] = (float)(ci.z - cj.z);
        sRel[tid * 3 + 2] = (float)(ci.w - cj.w);
    }
    // W <- tf32(Wd2)
    for (int e = tid; e < 4096; e += 256) {
        int k = e >> 5, s = (e & 31) * 4;
        float4 v = *(const float4*)&Wd2[(size_t)k * 128 + s];
        float4 o = {to_tf32(v.x), to_tf32(v.y), to_tf32(v.z), to_tf32(v.w)};
        *(float4*)&BufW[k * WPITCH + s] = o;
    }
    __syncthreads();

    // stage 1: A <- tf32(relu(rel @ Wd1 + bd1))
    for (int e = tid; e < 128 * 128; e += 256) {
        int r = e >> 7, c = e & 127;
        float v = sBd1[c] + sRel[r * 3] * sWd1[c] + sRel[r * 3 + 1] * sWd1[128 + c]
                + sRel[r * 3 + 2] * sWd1[256 + c];
        BufA[r * APITCH + c] = to_tf32(fmaxf(v, 0.f));
    }
    __syncthreads();

    float acc[4][4][4];

    // GEMM1: delta = h1 @ Wd2 + bd2 -> BufD (fp32)
    gemm128_mma(BufA, BufW, acc, wr, wc, g, t);
    #pragma unroll
    for (int mi = 0; mi < 4; mi++) {
        int r0 = wr * 64 + mi * 16 + g;
        #pragma unroll
        for (int ni = 0; ni < 4; ni++) {
            int c0 = wc * 32 + ni * 8 + 2 * t;
            float b0 = __ldg(&bd2[c0]), b1 = __ldg(&bd2[c0 + 1]);
            *(float2*)&BufD[r0 * APITCH + c0] =
                make_float2(acc[mi][ni][0] + b0, acc[mi][ni][1] + b1);
            *(float2*)&BufD[(r0 + 8) * APITCH + c0] =
                make_float2(acc[mi][ni][2] + b0, acc[mi][ni][3] + b1);
        }
    }
    __syncthreads();

    // A <- tf32(q - kf[g] + delta);  W <- tf32(Wg1)
    for (int e = tid; e < 4096; e += 256) {
        int r = e >> 5, s = (e & 31) * 4;
        int pl = r >> 4;
        float4 kv = *(const float4*)&g_kf[(size_t)sIdx[r] * 128 + s];
        float4 qv = *(const float4*)&sQ[pl * 128 + s];
        float4 dv = *(const float4*)&BufD[r * APITCH + s];
        float4 o;
        o.x = to_tf32(qv.x - kv.x + dv.x);
        o.y = to_tf32(qv.y - kv.y + dv.y);
        o.z = to_tf32(qv.z - kv.z + dv.z);
        o.w = to_tf32(qv.w - kv.w + dv.w);
        *(float4*)&BufA[r * APITCH + s] = o;
    }
    for (int e = tid; e < 4096; e += 256) {
        int k = e >> 5, s = (e & 31) * 4;
        float4 v = *(const float4*)&Wg1[(size_t)k * 128 + s];
        float4 o = {to_tf32(v.x), to_tf32(v.y), to_tf32(v.z), to_tf32(v.w)};
        *(float4*)&BufW[k * WPITCH + s] = o;
    }
    __syncthreads();

    // GEMM2: h2 = relu(apre @ Wg1 + bg1)
    gemm128_mma(BufA, BufW, acc, wr, wc, g, t);
    __syncthreads();
    #pragma unroll
    for (int mi = 0; mi < 4; mi++) {
        int r0 = wr * 64 + mi * 16 + g;
        #pragma unroll
        for (int ni = 0; ni < 4; ni++) {
            int c0 = wc * 32 + ni * 8 + 2 * t;
            float b0 = __ldg(&bg1[c0]), b1 = __ldg(&bg1[c0 + 1]);
            *(float2*)&BufA[r0 * APITCH + c0] =
                make_float2(to_tf32(fmaxf(acc[mi][ni][0] + b0, 0.f)),
                            to_tf32(fmaxf(acc[mi][ni][1] + b1, 0.f)));
            *(float2*)&BufA[(r0 + 8) * APITCH + c0] =
                make_float2(to_tf32(fmaxf(acc[mi][ni][2] + b0, 0.f)),
                            to_tf32(fmaxf(acc[mi][ni][3] + b1, 0.f)));
        }
    }
    for (int e = tid; e < 4096; e += 256) {
        int k = e >> 5, s = (e & 31) * 4;
        float4 v = *(const float4*)&Wg2[(size_t)k * 128 + s];
        float4 o = {to_tf32(v.x), to_tf32(v.y), to_tf32(v.z), to_tf32(v.w)};
        *(float4*)&BufW[k * WPITCH + s] = o;
    }
    __syncthreads();

    // GEMM3: a = h2 @ Wg2 + bg2
    gemm128_mma(BufA, BufW, acc, wr, wc, g, t);
    __syncthreads();
    #pragma unroll
    for (int mi = 0; mi < 4; mi++) {
        int r0 = wr * 64 + mi * 16 + g;
        #pragma unroll
        for (int ni = 0; ni < 4; ni++) {
            int c0 = wc * 32 + ni * 8 + 2 * t;
            float b0 = __ldg(&bg2[c0]), b1 = __ldg(&bg2[c0 + 1]);
            *(float2*)&BufA[r0 * APITCH + c0] =
                make_float2(acc[mi][ni][0] + b0, acc[mi][ni][1] + b1);
            *(float2*)&BufA[(r0 + 8) * APITCH + c0] =
                make_float2(acc[mi][ni][2] + b0, acc[mi][ni][3] + b1);
        }
    }
    // W <- gathered v
    for (int e = tid; e < 4096; e += 256) {
        int r = e >> 5, s = (e & 31) * 4;
        *(float4*)&BufW[r * WPITCH + s] =
            *(const float4*)&g_v[(size_t)sIdx[r] * 128 + s];
    }
    __syncthreads();

    // softmax over K per (point, channel) + aggregate
    for (int e = tid; e < 8 * 128; e += 256) {
        int pl = e >> 7, c = e & 127;
        int rb = pl * 16;
        float m = -1e30f;
        #pragma unroll
        for (int k = 0; k < 16; k++)
            m = fmaxf(m, BufA[(rb + k) * APITCH + c]);
        float s = 0.f, a2 = 0.f;
        #pragma unroll
        for (int k = 0; k < 16; k++) {
            int r = rb + k;
            float e2 = __expf(BufA[r * APITCH + c] - m);
            s += e2;
            a2 += e2 * (BufW[r * WPITCH + c] + BufD[r * APITCH + c]);
        }
        g_agg[(size_t)(p0 + pl) * 128 + c] = a2 / s;
    }
}

// ============================ down-proj: agg @ W_down + b_down ===================
__global__ __launch_bounds__(256) void down_kernel(const float* __restrict__ W,
                                                   const float* __restrict__ bias,
                                                   float* __restrict__ out) {
    __shared__ float As[16][128];
    __shared__ float Bs[16][64];
    int tid = threadIdx.x;
    int ty = tid >> 4, tx = tid & 15;
    int row0 = blockIdx.x * 128;
    float acc[8][4] = {};
    for (int kt = 0; kt < 128; kt += 16) {
        for (int e = tid; e < 512; e += 256) {
            int r = e >> 2, s = e & 3;
            float4 v = *(const float4*)&g_agg[(size_t)(row0 + r) * 128 + kt + s * 4];
            As[s * 4 + 0][r] = v.x; As[s * 4 + 1][r] = v.y;
            As[s * 4 + 2][r] = v.z; As[s * 4 + 3][r] = v.w;
        }
        if (tid < 256) {
            int k = tid >> 4, s = tid & 15;
            *(float4*)&Bs[k][s * 4] = *(const float4*)&W[(size_t)(kt + k) * 64 + s * 4];
        }
        __syncthreads();
        #pragma unroll
        for (int k = 0; k < 16; k++) {
            float4 a0 = *(const float4*)&As[k][ty * 8];
            float4 a1 = *(const float4*)&As[k][ty * 8 + 4];
            float4 b = *(const float4*)&Bs[k][tx * 4];
            float av[8] = {a0.x, a0.y, a0.z, a0.w, a1.x, a1.y, a1.z, a1.w};
            float bv[4] = {b.x, b.y, b.z, b.w};
            #pragma unroll
            for (int i = 0; i < 8; i++)
                #pragma unroll
                for (int j = 0; j < 4; j++)
                    acc[i][j] += av[i] * bv[j];
        }
        __syncthreads();
    }
    #pragma unroll
    for (int i = 0; i < 8; i++)
        #pragma unroll
        for (int j = 0; j < 4; j++)
            out[(size_t)(row0 + ty * 8 + i) * 64 + tx * 4 + j] =
                acc[i][j] + __ldg(&bias[tx * 4 + j]);
}

// ============================ final BN + residual ================================
__global__ __launch_bounds__(256) void final_kernel(const float* __restrict__ x,
                                                    const float* __restrict__ g2,
                                                    const float* __restrict__ be2,
                                                    float* __restrict__ out) {
    int e = blockIdx.x * 256 + threadIdx.x;
    if (e < TOT * IND) {
        int c = e & 63;
        float m = g_stats[c], is = g_stats[IND + c];
        out[e] = (out[e] - m) * is * g2[c] + be2[c] + x[e];
    }
}

// ============================ launch =============================================
extern "C" void kernel_launch(void* const* d_in, const int* in_sizes, int n_in,
                              void* d_out, int out_size) {
    const int*   coords  = (const int*)  d_in[0];
    const float* x       = (const float*)d_in[1];
    const float* W_top   = (const float*)d_in[2];
    const float* b_top   = (const float*)d_in[3];
    const float* g1      = (const float*)d_in[4];
    const float* be1     = (const float*)d_in[5];
    const float* W_phi   = (const float*)d_in[6];
    const float* W_psi   = (const float*)d_in[7];
    const float* W_alpha = (const float*)d_in[8];
    const float* Wd1     = (const float*)d_in[9];
    const float* bd1     = (const float*)d_in[10];
    const float* Wd2     = (const float*)d_in[11];
    const float* bd2     = (const float*)d_in[12];
    const float* Wg1     = (const float*)d_in[13];
    const float* bg1     = (const float*)d_in[14];
    const float* Wg2     = (const float*)d_in[15];
    const float* bg2     = (const float*)d_in[16];
    const float* W_down  = (const float*)d_in[17];
    const float* b_down  = (const float*)d_in[18];
    const float* g2      = (const float*)d_in[19];
    const float* be2     = (const float*)d_in[20];
    float* out = (float*)d_out;

    const size_t SMEM_F = (size_t)(128 * APITCH * 2 + 128 * WPITCH + 8 * 128
                                   + 128 * 3 + 384 + 128 + 128) * 4;
    const size_t SMEM_Q = (size_t)(128 * APITCH + 128 * WPITCH) * 4;
    cudaFuncSetAttribute(fused_kernel, cudaFuncAttributeMaxDynamicSharedMemorySize,
                         (int)SMEM_F);
    cudaFuncSetAttribute(qkv_kernel, cudaFuncAttributeMaxDynamicSharedMemorySize,
                         (int)SMEM_Q);

    void* p_t = nullptr;
    cudaGetSymbolAddress(&p_t, g_t);

    ball_kernel<<<TOT / 128, 128>>>(coords);
    topproj_kernel<<<TOT / 128, 256>>>(x, W_top, b_top);
    bn_partial_k<128><<<128, 256>>>((const float*)p_t);
    bn_finalize_k<128><<<1, 256>>>();
    qkv_kernel<<<dim3(TOT / 128, 3), 256, SMEM_Q>>>(g1, be1, W_phi, W_psi, W_alpha);
    fused_kernel<<<TOT / 8, 256, SMEM_F>>>(coords, Wd1, bd1, Wd2, bd2,
                                           Wg1, bg1, Wg2, bg2);
    down_kernel<<<TOT / 128, 256>>>(W_down, b_down, out);
    bn_partial_k<64><<<128, 256>>>((const float*)out);
    bn_finalize_k<64><<<1, 256>>>();
    final_kernel<<<(TOT * IND + 255) / 256, 256>>>(x, g2, be2, out);
}

// round 5
// speedup vs baseline: 2.3262x; 1.3104x over previous
#include <cuda_runtime.h>
#include <cuda_bf16.h>
#include <cstdint>
#include <math.h>

#define TOT   16384
#define NPTS  4096
#define KNN   16
#define HD    128
#define IND   64
#define APITCH 132   // A buffer: banks g*4+t unique for A frag loads
#define WPITCH 136   // W buffer: banks t*8+g unique for B frag loads

// ---------------- device scratch ------------------------------------------------
__device__ int   g_idx[TOT * KNN];
__device__ float g_t  [TOT * HD];
__device__ float g_q  [TOT * HD];
__device__ float g_kf [TOT * HD];
__device__ float g_v  [TOT * HD];
__device__ float g_agg[TOT * HD];
__device__ float g_part[128 * 2 * HD];
__device__ float g_stats[2 * HD];

__device__ __forceinline__ float to_tf32(float x) {
    unsigned int r;
    asm("cvt.rna.tf32.f32 %0, %1;" : "=r"(r) : "f"(x));
    return __uint_as_float(r);
}

// ============================ ball query =========================================
__global__ __launch_bounds__(128) void ball_kernel(const int* __restrict__ coords) {
    __shared__ int sP[NPTS];
    int b = (blockIdx.x * 128) / NPTS;
    int base = b * NPTS;
    for (int j = threadIdx.x; j < NPTS; j += 128) {
        int4 c = *(const int4*)&coords[(size_t)(base + j) * 4];
        sP[j] = c.y | (c.z << 8) | (c.w << 16);
    }
    __syncthreads();
    int qi = blockIdx.x * 128 + threadIdx.x;
    int me = sP[qi - base];
    int qx = me & 255, qy = (me >> 8) & 255, qz = me >> 16;
    int cnt = 0, first = 0;
    int* out = g_idx + (size_t)qi * KNN;
    #pragma unroll 8
    for (int j = 0; j < NPTS; j++) {
        int p = sP[j];
        int dx = qx - (p & 255);
        int dy = qy - ((p >> 8) & 255);
        int dz = qz - (p >> 16);
        int d2 = dx * dx + dy * dy + dz * dz;
        if (d2 <= 100 && cnt < KNN) {
            int gj = base + j;
            out[cnt] = gj;
            if (cnt == 0) first = gj;
            cnt++;
        }
    }
    for (int k = cnt; k < KNN; k++) out[k] = first;
}

// ============================ GEMM: t = x @ W_top + b_top  (16384x64x128) ========
__global__ __launch_bounds__(256) void topproj_kernel(const float* __restrict__ x,
                                                      const float* __restrict__ W,
                                                      const float* __restrict__ bias) {
    __shared__ float As[16][128];
    __shared__ float Bs[16][128];
    int tid = threadIdx.x;
    int ty = tid >> 4, tx = tid & 15;
    int row0 = blockIdx.x * 128;
    float acc[8][8] = {};
    for (int kt = 0; kt < 64; kt += 16) {
        for (int e = tid; e < 512; e += 256) {
            int r = e >> 2, s = e & 3;
            float4 v = *(const float4*)&x[(size_t)(row0 + r) * 64 + kt + s * 4];
            As[s * 4 + 0][r] = v.x; As[s * 4 + 1][r] = v.y;
            As[s * 4 + 2][r] = v.z; As[s * 4 + 3][r] = v.w;
        }
        for (int e = tid; e < 512; e += 256) {
            int k = e >> 5, s = e & 31;
            *(float4*)&Bs[k][s * 4] = *(const float4*)&W[(size_t)(kt + k) * 128 + s * 4];
        }
        __syncthreads();
        #pragma unroll
        for (int k = 0; k < 16; k++) {
            float4 a0 = *(const float4*)&As[k][ty * 8];
            float4 a1 = *(const float4*)&As[k][ty * 8 + 4];
            float4 b0 = *(const float4*)&Bs[k][tx * 8];
            float4 b1 = *(const float4*)&Bs[k][tx * 8 + 4];
            float av[8] = {a0.x, a0.y, a0.z, a0.w, a1.x, a1.y, a1.z, a1.w};
            float bv[8] = {b0.x, b0.y, b0.z, b0.w, b1.x, b1.y, b1.z, b1.w};
            #pragma unroll
            for (int i = 0; i < 8; i++)
                #pragma unroll
                for (int j = 0; j < 8; j++)
                    acc[i][j] += av[i] * bv[j];
        }
        __syncthreads();
    }
    #pragma unroll
    for (int i = 0; i < 8; i++)
        #pragma unroll
        for (int j = 0; j < 8; j++)
            g_t[(size_t)(row0 + ty * 8 + i) * 128 + tx * 8 + j] =
                acc[i][j] + __ldg(&bias[tx * 8 + j]);
}

// ============================ BN partial / finalize ==============================
template <int C>
__global__ __launch_bounds__(256) void bn_partial_k(const float* __restrict__ src) {
    constexpr int SUB = 256 / C;
    int c = threadIdx.x % C, sub = threadIdx.x / C;
    int row0 = blockIdx.x * 128;
    float s = 0.f, ss = 0.f;
    for (int r = sub; r < 128; r += SUB) {
        float v = src[(size_t)(row0 + r) * C + c];
        s += v; ss += v * v;
    }
    __shared__ float red[2][256];
    red[0][threadIdx.x] = s; red[1][threadIdx.x] = ss;
    __syncthreads();
    if (sub == 0) {
        for (int u = 1; u < SUB; u++) { s += red[0][u * C + c]; ss += red[1][u * C + c]; }
        g_part[blockIdx.x * 2 * C + c]     = s;
        g_part[blockIdx.x * 2 * C + C + c] = ss;
    }
}

template <int C>
__global__ __launch_bounds__(256) void bn_finalize_k() {
    constexpr int NSUB = 256 / C;
    int c = threadIdx.x % C, sub = threadIdx.x / C;
    float s = 0.f, ss = 0.f;
    #pragma unroll 4
    for (int b = sub; b < 128; b += NSUB) {
        s  += g_part[b * 2 * C + c];
        ss += g_part[b * 2 * C + C + c];
    }
    __shared__ float red[2][256];
    red[0][threadIdx.x] = s; red[1][threadIdx.x] = ss;
    __syncthreads();
    if (sub == 0) {
        #pragma unroll
        for (int u = 1; u < NSUB; u++) { s += red[0][u * C + c]; ss += red[1][u * C + c]; }
        float m = s / (float)TOT;
        float var = ss / (float)TOT - m * m;
        g_stats[c]     = m;
        g_stats[C + c] = rsqrtf(var + 1e-5f);
    }
}

// ============================ tf32 mma GEMM core =================================
// 128x128x128; 16 warps; warp tile 32x32 (wr=wid>>2 in 0..3, wc=wid&3); m16n8k8.
// A [128][APITCH] row-major tf32; W [128][WPITCH] k-major tf32.
template <int MI>
__device__ __forceinline__ void gemm_mma(const float* __restrict__ A,
                                         const float* __restrict__ W,
                                         float acc[MI][4][4],
                                         int wr, int wc, int g, int t) {
    #pragma unroll
    for (int i = 0; i < MI; i++)
        #pragma unroll
        for (int j = 0; j < 4; j++)
            #pragma unroll
            for (int r = 0; r < 4; r++) acc[i][j][r] = 0.f;
    #pragma unroll 4
    for (int kk = 0; kk < 16; kk++) {
        const int k0 = kk * 8;
        unsigned int a[MI][4];
        #pragma unroll
        for (int mi = 0; mi < MI; mi++) {
            const float* ap = A + (size_t)(wr * (MI * 16) + mi * 16 + g) * APITCH + k0 + t;
            a[mi][0] = __float_as_uint(ap[0]);
            a[mi][1] = __float_as_uint(ap[8 * APITCH]);
            a[mi][2] = __float_as_uint(ap[4]);
            a[mi][3] = __float_as_uint(ap[8 * APITCH + 4]);
        }
        #pragma unroll
        for (int ni = 0; ni < 4; ni++) {
            const float* bp = W + (size_t)(k0 + t) * WPITCH + wc * 32 + ni * 8 + g;
            unsigned int b0 = __float_as_uint(bp[0]);
            unsigned int b1 = __float_as_uint(bp[4 * WPITCH]);
            #pragma unroll
            for (int mi = 0; mi < MI; mi++) {
                asm volatile(
                    "mma.sync.aligned.m16n8k8.row.col.f32.tf32.tf32.f32 "
                    "{%0,%1,%2,%3}, {%4,%5,%6,%7}, {%8,%9}, {%0,%1,%2,%3};\n"
                    : "+f"(acc[mi][ni][0]), "+f"(acc[mi][ni][1]),
                      "+f"(acc[mi][ni][2]), "+f"(acc[mi][ni][3])
                    : "r"(a[mi][0]), "r"(a[mi][1]), "r"(a[mi][2]), "r"(a[mi][3]),
                      "r"(b0), "r"(b1));
            }
        }
    }
}

// ============== q,kf,v = normalize(t) @ {W_phi,W_psi,W_alpha} (mma tf32) =========
// One block per 128-row slab; loops over the 3 weight matrices, staging A once.
__global__ __launch_bounds__(512) void qkv_kernel(const float* __restrict__ g1v,
                                                  const float* __restrict__ be1,
                                                  const float* __restrict__ Wphi,
                                                  const float* __restrict__ Wpsi,
                                                  const float* __restrict__ Walpha) {
    extern __shared__ float sm[];
    float* BufA = sm;                    // [128][APITCH]
    float* BufW = BufA + 128 * APITCH;   // [128][WPITCH]
    __shared__ float sScale[128], sShift[128];
    int tid = threadIdx.x;
    if (tid < 128) {
        float m = g_stats[tid], is = g_stats[128 + tid];
        float sc = is * g1v[tid];
        sScale[tid] = sc;
        sShift[tid] = be1[tid] - m * sc;
    }
    __syncthreads();
    int row0 = blockIdx.x * 128;
    for (int e = tid; e < 4096; e += 512) {
        int r = e >> 5, s = (e & 31) * 4;
        float4 v = *(const float4*)&g_t[(size_t)(row0 + r) * 128 + s];
        float4 o;
        o.x = to_tf32(v.x * sScale[s] + sShift[s]);
        o.y = to_tf32(v.y * sScale[s + 1] + sShift[s + 1]);
        o.z = to_tf32(v.z * sScale[s + 2] + sShift[s + 2]);
        o.w = to_tf32(v.w * sScale[s + 3] + sShift[s + 3]);
        *(float4*)&BufA[r * APITCH + s] = o;
    }

    int wid = tid >> 5, lane = tid & 31;
    int wr = wid >> 2, wc = wid & 3;
    int g = lane >> 2, t = lane & 3;

    #pragma unroll 1
    for (int widx = 0; widx < 3; widx++) {
        const float* W = (widx == 0) ? Wphi : (widx == 1) ? Wpsi : Walpha;
        float* out = (widx == 0) ? g_q : (widx == 1) ? g_kf : g_v;
        for (int e = tid; e < 4096; e += 512) {
            int k = e >> 5, s = (e & 31) * 4;
            float4 v = *(const float4*)&W[(size_t)k * 128 + s];
            float4 o = {to_tf32(v.x), to_tf32(v.y), to_tf32(v.z), to_tf32(v.w)};
            *(float4*)&BufW[k * WPITCH + s] = o;
        }
        __syncthreads();

        float acc[2][4][4];
        gemm_mma<2>(BufA, BufW, acc, wr, wc, g, t);

        #pragma unroll
        for (int mi = 0; mi < 2; mi++) {
            int r0 = row0 + wr * 32 + mi * 16 + g;
            #pragma unroll
            for (int ni = 0; ni < 4; ni++) {
                int c0 = wc * 32 + ni * 8 + 2 * t;
                *(float2*)&out[(size_t)r0 * 128 + c0] =
                    make_float2(acc[mi][ni][0], acc[mi][ni][1]);
                *(float2*)&out[(size_t)(r0 + 8) * 128 + c0] =
                    make_float2(acc[mi][ni][2], acc[mi][ni][3]);
            }
        }
        __syncthreads();   // before BufW overwrite next iteration
    }
}

// ============================ fused per-point attention (mma tf32) ==============
// 8 points/block, 512 threads, 16 warps, warp tile 32x32. Delta lives in regs;
// softmax over K=16 via butterfly shuffles across the 8 g-lanes.
__global__ __launch_bounds__(512) void fused_kernel(const int* __restrict__ coords,
                                                    const float* __restrict__ Wd1,
                                                    const float* __restrict__ bd1,
                                                    const float* __restrict__ Wd2,
                                                    const float* __restrict__ bd2,
                                                    const float* __restrict__ Wg1,
                                                    const float* __restrict__ bg1,
                                                    const float* __restrict__ Wg2,
                                                    const float* __restrict__ bg2) {
    extern __shared__ float sm[];
    float* BufA = sm;                      // [128][APITCH] mma A operand
    float* BufW = BufA + 128 * APITCH;     // [128][WPITCH] weights
    float* sQ   = BufW + 128 * WPITCH;     // [8][128]
    float* sRel = sQ + 8 * 128;            // [128][3]
    float* sWd1 = sRel + 128 * 3;          // [3][128]
    float* sBd1 = sWd1 + 384;              // [128]
    int*   sIdx = (int*)(sBd1 + 128);      // [128]

    int tid = threadIdx.x;
    int p0 = blockIdx.x * 8;
    int wid = tid >> 5, lane = tid & 31;
    int wr = wid >> 2, wc = wid & 3;
    int g = lane >> 2, t = lane & 3;

    if (tid < 128) {
        sIdx[tid] = g_idx[(size_t)p0 * KNN + tid];
        sBd1[tid] = bd1[tid];
    }
    if (tid < 384) sWd1[tid] = Wd1[tid];
    if (tid < 256) {
        int pp = tid >> 5, s = (tid & 31) * 4;
        *(float4*)&sQ[pp * 128 + s] = *(const float4*)&g_q[(size_t)(p0 + pp) * 128 + s];
    }
    __syncthreads();

    if (tid < 128) {
        int i = p0 + (tid >> 4);
        int j = sIdx[tid];
        int4 ci = *(const int4*)&coords[(size_t)i * 4];
        int4 cj = *(const int4*)&coords[(size_t)j * 4];
        sRel[tid * 3 + 0] = (float)(ci.y - cj.y);
        sRel[tid * 3 + 1] = (float)(ci.z - cj.z);
        sRel[tid * 3 + 2] = (float)(ci.w - cj.w);
    }
    // BufW <- tf32(Wd2)
    for (int e = tid; e < 4096; e += 512) {
        int k = e >> 5, s = (e & 31) * 4;
        float4 v = *(const float4*)&Wd2[(size_t)k * 128 + s];
        float4 o = {to_tf32(v.x), to_tf32(v.y), to_tf32(v.z), to_tf32(v.w)};
        *(float4*)&BufW[k * WPITCH + s] = o;
    }
    __syncthreads();

    // stage 1: BufA <- tf32(relu(rel @ Wd1 + bd1))
    for (int e = tid; e < 128 * 128; e += 512) {
        int r = e >> 7, c = e & 127;
        float v = sBd1[c] + sRel[r * 3] * sWd1[c] + sRel[r * 3 + 1] * sWd1[128 + c]
                + sRel[r * 3 + 2] * sWd1[256 + c];
        BufA[r * APITCH + c] = to_tf32(fmaxf(v, 0.f));
    }
    __syncthreads();

    // GEMM1: delta = h1 @ Wd2 + bd2  (kept in registers)
    float dlt[2][4][4];
    gemm_mma<2>(BufA, BufW, dlt, wr, wc, g, t);
    #pragma unroll
    for (int mi = 0; mi < 2; mi++)
        #pragma unroll
        for (int ni = 0; ni < 4; ni++) {
            int c0 = wc * 32 + ni * 8 + 2 * t;
            float b0 = __ldg(&bd2[c0]), b1 = __ldg(&bd2[c0 + 1]);
            dlt[mi][ni][0] += b0; dlt[mi][ni][1] += b1;
            dlt[mi][ni][2] += b0; dlt[mi][ni][3] += b1;
        }
    __syncthreads();   // all reads of BufA/BufW complete

    // epilogue1: BufA <- tf32(q - kf[g] + delta); BufW <- tf32(Wg1)
    #pragma unroll
    for (int mi = 0; mi < 2; mi++) {
        int r0 = wr * 32 + mi * 16 + g;
        int r1 = r0 + 8;
        int pl = wr * 2 + mi;
        int gi0 = sIdx[r0], gi1 = sIdx[r1];
        #pragma unroll
        for (int ni = 0; ni < 4; ni++) {
            int c0 = wc * 32 + ni * 8 + 2 * t;
            float2 k0 = *(const float2*)&g_kf[(size_t)gi0 * 128 + c0];
            float2 k1 = *(const float2*)&g_kf[(size_t)gi1 * 128 + c0];
            float q0 = sQ[pl * 128 + c0], q1 = sQ[pl * 128 + c0 + 1];
            *(float2*)&BufA[r0 * APITCH + c0] =
                make_float2(to_tf32(q0 - k0.x + dlt[mi][ni][0]),
                            to_tf32(q1 - k0.y + dlt[mi][ni][1]));
            *(float2*)&BufA[r1 * APITCH + c0] =
                make_float2(to_tf32(q0 - k1.x + dlt[mi][ni][2]),
                            to_tf32(q1 - k1.y + dlt[mi][ni][3]));
        }
    }
    for (int e = tid; e < 4096; e += 512) {
        int k = e >> 5, s = (e & 31) * 4;
        float4 v = *(const float4*)&Wg1[(size_t)k * 128 + s];
        float4 o = {to_tf32(v.x), to_tf32(v.y), to_tf32(v.z), to_tf32(v.w)};
        *(float4*)&BufW[k * WPITCH + s] = o;
    }
    __syncthreads();

    // GEMM2: h2 = relu(apre @ Wg1 + bg1)
    float acc2[2][4][4];
    gemm_mma<2>(BufA, BufW, acc2, wr, wc, g, t);
    __syncthreads();
    #pragma unroll
    for (int mi = 0; mi < 2; mi++) {
        int r0 = wr * 32 + mi * 16 + g;
        #pragma unroll
        for (int ni = 0; ni < 4; ni++) {
            int c0 = wc * 32 + ni * 8 + 2 * t;
            float b0 = __ldg(&bg1[c0]), b1 = __ldg(&bg1[c0 + 1]);
            *(float2*)&BufA[r0 * APITCH + c0] =
                make_float2(to_tf32(fmaxf(acc2[mi][ni][0] + b0, 0.f)),
                            to_tf32(fmaxf(acc2[mi][ni][1] + b1, 0.f)));
            *(float2*)&BufA[(r0 + 8) * APITCH + c0] =
                make_float2(to_tf32(fmaxf(acc2[mi][ni][2] + b0, 0.f)),
                            to_tf32(fmaxf(acc2[mi][ni][3] + b1, 0.f)));
        }
    }
    for (int e = tid; e < 4096; e += 512) {
        int k = e >> 5, s = (e & 31) * 4;
        float4 v = *(const float4*)&Wg2[(size_t)k * 128 + s];
        float4 o = {to_tf32(v.x), to_tf32(v.y), to_tf32(v.z), to_tf32(v.w)};
        *(float4*)&BufW[k * WPITCH + s] = o;
    }
    __syncthreads();

    // GEMM3: logits = h2 @ Wg2 (+bg2 below)
    gemm_mma<2>(BufA, BufW, acc2, wr, wc, g, t);

    // softmax over K + aggregate, all in registers/shuffles
    #pragma unroll
    for (int mi = 0; mi < 2; mi++) {
        int r0 = wr * 32 + mi * 16 + g;
        int r1 = r0 + 8;
        int pl = wr * 2 + mi;
        int gi0 = sIdx[r0], gi1 = sIdx[r1];
        #pragma unroll
        for (int ni = 0; ni < 4; ni++) {
            int c0 = wc * 32 + ni * 8 + 2 * t;
            float b0 = __ldg(&bg2[c0]), b1 = __ldg(&bg2[c0 + 1]);
            float l00 = acc2[mi][ni][0] + b0, l01 = acc2[mi][ni][1] + b1;
            float l10 = acc2[mi][ni][2] + b0, l11 = acc2[mi][ni][3] + b1;
            float2 v0 = *(const float2*)&g_v[(size_t)gi0 * 128 + c0];
            float2 v1 = *(const float2*)&g_v[(size_t)gi1 * 128 + c0];
            float w00 = v0.x + dlt[mi][ni][0], w01 = v0.y + dlt[mi][ni][1];
            float w10 = v1.x + dlt[mi][ni][2], w11 = v1.y + dlt[mi][ni][3];

            float m0 = fmaxf(l00, l10);
            m0 = fmaxf(m0, __shfl_xor_sync(0xffffffffu, m0, 4));
            m0 = fmaxf(m0, __shfl_xor_sync(0xffffffffu, m0, 8));
            m0 = fmaxf(m0, __shfl_xor_sync(0xffffffffu, m0, 16));
            float m1 = fmaxf(l01, l11);
            m1 = fmaxf(m1, __shfl_xor_sync(0xffffffffu, m1, 4));
            m1 = fmaxf(m1, __shfl_xor_sync(0xffffffffu, m1, 8));
            m1 = fmaxf(m1, __shfl_xor_sync(0xffffffffu, m1, 16));

            float e00 = __expf(l00 - m0), e10 = __expf(l10 - m0);
            float e01 = __expf(l01 - m1), e11 = __expf(l11 - m1);
            float s0 = e00 + e10, s1 = e01 + e11;
            float a0 = e00 * w00 + e10 * w10;
            float a1 = e01 * w01 + e11 * w11;
            s0 += __shfl_xor_sync(0xffffffffu, s0, 4);
            s0 += __shfl_xor_sync(0xffffffffu, s0, 8);
            s0 += __shfl_xor_sync(0xffffffffu, s0, 16);
            s1 += __shfl_xor_sync(0xffffffffu, s1, 4);
            s1 += __shfl_xor_sync(0xffffffffu, s1, 8);
            s1 += __shfl_xor_sync(0xffffffffu, s1, 16);
            a0 += __shfl_xor_sync(0xffffffffu, a0, 4);
            a0 += __shfl_xor_sync(0xffffffffu, a0, 8);
            a0 += __shfl_xor_sync(0xffffffffu, a0, 16);
            a1 += __shfl_xor_sync(0xffffffffu, a1, 4);
            a1 += __shfl_xor_sync(0xffffffffu, a1, 8);
            a1 += __shfl_xor_sync(0xffffffffu, a1, 16);

            if (g == 0)
                *(float2*)&g_agg[(size_t)(p0 + pl) * 128 + c0] =
                    make_float2(a0 / s0, a1 / s1);
        }
    }
}

// ============================ down-proj: agg @ W_down + b_down ===================
__global__ __launch_bounds__(256) void down_kernel(const float* __restrict__ W,
                                                   const float* __restrict__ bias,
                                                   float* __restrict__ out) {
    __shared__ float As[16][128];
    __shared__ float Bs[16][64];
    int tid = threadIdx.x;
    int ty = tid >> 4, tx = tid & 15;
    int row0 = blockIdx.x * 128;
    float acc[8][4] = {};
    for (int kt = 0; kt < 128; kt += 16) {
        for (int e = tid; e < 512; e += 256) {
            int r = e >> 2, s = e & 3;
            float4 v = *(const float4*)&g_agg[(size_t)(row0 + r) * 128 + kt + s * 4];
            As[s * 4 + 0][r] = v.x; As[s * 4 + 1][r] = v.y;
            As[s * 4 + 2][r] = v.z; As[s * 4 + 3][r] = v.w;
        }
        if (tid < 256) {
            int k = tid >> 4, s = tid & 15;
            *(float4*)&Bs[k][s * 4] = *(const float4*)&W[(size_t)(kt + k) * 64 + s * 4];
        }
        __syncthreads();
        #pragma unroll
        for (int k = 0; k < 16; k++) {
            float4 a0 = *(const float4*)&As[k][ty * 8];
            float4 a1 = *(const float4*)&As[k][ty * 8 + 4];
            float4 b = *(const float4*)&Bs[k][tx * 4];
            float av[8] = {a0.x, a0.y, a0.z, a0.w, a1.x, a1.y, a1.z, a1.w};
            float bv[4] = {b.x, b.y, b.z, b.w};
            #pragma unroll
            for (int i = 0; i < 8; i++)
                #pragma unroll
                for (int j = 0; j < 4; j++)
                    acc[i][j] += av[i] * bv[j];
        }
        __syncthreads();
    }
    #pragma unroll
    for (int i = 0; i < 8; i++)
        #pragma unroll
        for (int j = 0; j < 4; j++)
            out[(size_t)(row0 + ty * 8 + i) * 64 + tx * 4 + j] =
                acc[i][j] + __ldg(&bias[tx * 4 + j]);
}

// ============================ final BN + residual ================================
__global__ __launch_bounds__(256) void final_kernel(const float* __restrict__ x,
                                                    const float* __restrict__ g2,
                                                    const float* __restrict__ be2,
                                                    float* __restrict__ out) {
    int e = blockIdx.x * 256 + threadIdx.x;
    if (e < TOT * IND) {
        int c = e & 63;
        float m = g_stats[c], is = g_stats[IND + c];
        out[e] = (out[e] - m) * is * g2[c] + be2[c] + x[e];
    }
}

// ============================ launch =============================================
extern "C" void kernel_launch(void* const* d_in, const int* in_sizes, int n_in,
                              void* d_out, int out_size) {
    const int*   coords  = (const int*)  d_in[0];
    const float* x       = (const float*)d_in[1];
    const float* W_top   = (const float*)d_in[2];
    const float* b_top   = (const float*)d_in[3];
    const float* g1      = (const float*)d_in[4];
    const float* be1     = (const float*)d_in[5];
    const float* W_phi   = (const float*)d_in[6];
    const float* W_psi   = (const float*)d_in[7];
    const float* W_alpha = (const float*)d_in[8];
    const float* Wd1     = (const float*)d_in[9];
    const float* bd1     = (const float*)d_in[10];
    const float* Wd2     = (const float*)d_in[11];
    const float* bd2     = (const float*)d_in[12];
    const float* Wg1     = (const float*)d_in[13];
    const float* bg1     = (const float*)d_in[14];
    const float* Wg2     = (const float*)d_in[15];
    const float* bg2     = (const float*)d_in[16];
    const float* W_down  = (const float*)d_in[17];
    const float* b_down  = (const float*)d_in[18];
    const float* g2      = (const float*)d_in[19];
    const float* be2     = (const float*)d_in[20];
    float* out = (float*)d_out;

    const size_t SMEM_F = (size_t)(128 * APITCH + 128 * WPITCH + 8 * 128
                                   + 128 * 3 + 384 + 128 + 128) * 4;
    const size_t SMEM_Q = (size_t)(128 * APITCH + 128 * WPITCH) * 4;
    cudaFuncSetAttribute(fused_kernel, cudaFuncAttributeMaxDynamicSharedMemorySize,
                         (int)SMEM_F);
    cudaFuncSetAttribute(qkv_kernel, cudaFuncAttributeMaxDynamicSharedMemorySize,
                         (int)SMEM_Q);

    void* p_t = nullptr;
    cudaGetSymbolAddress(&p_t, g_t);

    ball_kernel<<<TOT / 128, 128>>>(coords);
    topproj_kernel<<<TOT / 128, 256>>>(x, W_top, b_top);
    bn_partial_k<128><<<128, 256>>>((const float*)p_t);
    bn_finalize_k<128><<<1, 256>>>();
    qkv_kernel<<<TOT / 128, 512, SMEM_Q>>>(g1, be1, W_phi, W_psi, W_alpha);
    fused_kernel<<<TOT / 8, 512, SMEM_F>>>(coords, Wd1, bd1, Wd2, bd2,
                                           Wg1, bg1, Wg2, bg2);
    down_kernel<<<TOT / 128, 256>>>(W_down, b_down, out);
    bn_partial_k<64><<<128, 256>>>((const float*)out);
    bn_finalize_k<64><<<1, 256>>>();
    final_kernel<<<(TOT * IND + 255) / 256, 256>>>(x, g2, be2, out);
}

// round 6
// speedup vs baseline: 2.5552x; 1.0984x over previous
#include <cuda_runtime.h>
#include <cuda_bf16.h>
#include <cstdint>
#include <math.h>

#define TOT   16384
#define NPTS  4096
#define KNN   16
#define HD    128
#define IND   64
#define APITCH 132   // A buffer: banks g*4+t unique for A frag loads
#define WPITCH 136   // W buffer: banks t*8+g unique for B frag loads

// ---------------- device scratch ------------------------------------------------
__device__ int   g_idx[TOT * KNN];
__device__ float g_t  [TOT * HD];
__device__ float g_q  [TOT * HD];
__device__ float g_kf [TOT * HD];
__device__ float g_v  [TOT * HD];
__device__ float g_agg[TOT * HD];
__device__ float g_part[128 * 2 * HD];
__device__ float g_stats[2 * HD];
__device__ float g_wtf[3 * HD * HD];        // tf32 pre-converted Wd2, Wg1, Wg2
__device__ unsigned int g_tick1;
__device__ unsigned int g_tick2;

__device__ __forceinline__ float to_tf32(float x) {
    unsigned int r;
    asm("cvt.rna.tf32.f32 %0, %1;" : "=r"(r) : "f"(x));
    return __uint_as_float(r);
}

__device__ __forceinline__ void cp16(void* dst_smem, const void* src) {
    unsigned int d = (unsigned int)__cvta_generic_to_shared(dst_smem);
    asm volatile("cp.async.cg.shared.global [%0], [%1], 16;\n" :: "r"(d), "l"(src));
}
__device__ __forceinline__ void cp_commit() {
    asm volatile("cp.async.commit_group;\n");
}
template <int N>
__device__ __forceinline__ void cp_wait() {
    asm volatile("cp.async.wait_group %0;\n" :: "n"(N));
}

// ============================ weight pre-convert =================================
__global__ __launch_bounds__(512) void conv_kernel(const float* __restrict__ Wd2,
                                                   const float* __restrict__ Wg1,
                                                   const float* __restrict__ Wg2) {
    int e = blockIdx.x * 512 + threadIdx.x;            // one float4 each
    const float* srcs[3] = {Wd2, Wg1, Wg2};
    int m = e / 4096, o = (e % 4096) * 4;
    if (m < 3) {
        float4 v = *(const float4*)&srcs[m][o];
        float4 w = {to_tf32(v.x), to_tf32(v.y), to_tf32(v.z), to_tf32(v.w)};
        *(float4*)&g_wtf[m * 16384 + o] = w;
    }
}

// ============================ ball query =========================================
__global__ __launch_bounds__(128) void ball_kernel(const int* __restrict__ coords) {
    __shared__ int sP[NPTS];
    int b = (blockIdx.x * 128) / NPTS;
    int base = b * NPTS;
    for (int j = threadIdx.x; j < NPTS; j += 128) {
        int4 c = *(const int4*)&coords[(size_t)(base + j) * 4];
        sP[j] = c.y | (c.z << 8) | (c.w << 16);
    }
    __syncthreads();
    int qi = blockIdx.x * 128 + threadIdx.x;
    int me = sP[qi - base];
    int qx = me & 255, qy = (me >> 8) & 255, qz = me >> 16;
    int cnt = 0, first = 0;
    int* out = g_idx + (size_t)qi * KNN;
    #pragma unroll 8
    for (int j = 0; j < NPTS; j++) {
        int p = sP[j];
        int dx = qx - (p & 255);
        int dy = qy - ((p >> 8) & 255);
        int dz = qz - (p >> 16);
        int d2 = dx * dx + dy * dy + dz * dz;
        if (d2 <= 100 && cnt < KNN) {
            int gj = base + j;
            out[cnt] = gj;
            if (cnt == 0) first = gj;
            cnt++;
        }
    }
    for (int k = cnt; k < KNN; k++) out[k] = first;
}

// ================ t = x @ W_top + b_top, fused BN partials + finalize ===========
__global__ __launch_bounds__(256) void topproj_kernel(const float* __restrict__ x,
                                                      const float* __restrict__ W,
                                                      const float* __restrict__ bias) {
    __shared__ float As[16][128];
    __shared__ float Bs[16][128];
    __shared__ float redS[16][128];
    __shared__ float redSS[16][128];
    __shared__ bool  sLast;
    int tid = threadIdx.x;
    int ty = tid >> 4, tx = tid & 15;
    int row0 = blockIdx.x * 128;
    float acc[8][8] = {};
    for (int kt = 0; kt < 64; kt += 16) {
        for (int e = tid; e < 512; e += 256) {
            int r = e >> 2, s = e & 3;
            float4 v = *(const float4*)&x[(size_t)(row0 + r) * 64 + kt + s * 4];
            As[s * 4 + 0][r] = v.x; As[s * 4 + 1][r] = v.y;
            As[s * 4 + 2][r] = v.z; As[s * 4 + 3][r] = v.w;
        }
        for (int e = tid; e < 512; e += 256) {
            int k = e >> 5, s = e & 31;
            *(float4*)&Bs[k][s * 4] = *(const float4*)&W[(size_t)(kt + k) * 128 + s * 4];
        }
        __syncthreads();
        #pragma unroll
        for (int k = 0; k < 16; k++) {
            float4 a0 = *(const float4*)&As[k][ty * 8];
            float4 a1 = *(const float4*)&As[k][ty * 8 + 4];
            float4 b0 = *(const float4*)&Bs[k][tx * 8];
            float4 b1 = *(const float4*)&Bs[k][tx * 8 + 4];
            float av[8] = {a0.x, a0.y, a0.z, a0.w, a1.x, a1.y, a1.z, a1.w};
            float bv[8] = {b0.x, b0.y, b0.z, b0.w, b1.x, b1.y, b1.z, b1.w};
            #pragma unroll
            for (int i = 0; i < 8; i++)
                #pragma unroll
                for (int j = 0; j < 8; j++)
                    acc[i][j] += av[i] * bv[j];
        }
        __syncthreads();
    }
    #pragma unroll
    for (int j = 0; j < 8; j++) {
        float b = __ldg(&bias[tx * 8 + j]);
        float s = 0.f, ss = 0.f;
        #pragma unroll
        for (int i = 0; i < 8; i++) {
            float v = acc[i][j] + b;
            g_t[(size_t)(row0 + ty * 8 + i) * 128 + tx * 8 + j] = v;
            s += v; ss += v * v;
        }
        redS[ty][tx * 8 + j] = s;
        redSS[ty][tx * 8 + j] = ss;
    }
    __syncthreads();
    if (tid < 128) {
        float s = 0.f, ss = 0.f;
        #pragma unroll
        for (int u = 0; u < 16; u++) { s += redS[u][tid]; ss += redSS[u][tid]; }
        g_part[blockIdx.x * 256 + tid]       = s;
        g_part[blockIdx.x * 256 + 128 + tid] = ss;
    }
    __threadfence();
    __syncthreads();
    if (tid == 0)
        sLast = (atomicAdd(&g_tick1, 1u) == gridDim.x - 1);
    __syncthreads();
    if (sLast) {
        int c = tid & 127, sub = tid >> 7;   // 2 subs x 128 channels
        float s = 0.f, ss = 0.f;
        for (int b = sub; b < 128; b += 2) {
            s  += g_part[b * 256 + c];
            ss += g_part[b * 256 + 128 + c];
        }
        redS[0][tid & 127] = 0.f;  // (unused slot safety)
        // reduce the 2 subs via shared
        redS[sub][c] = s; redSS[sub][c] = ss;
        __syncthreads();
        if (tid < 128) {
            float S = redS[0][tid] + redS[1][tid];
            float SS = redSS[0][tid] + redSS[1][tid];
            float m = S / (float)TOT;
            float var = SS / (float)TOT - m * m;
            g_stats[tid]       = m;
            g_stats[128 + tid] = rsqrtf(var + 1e-5f);
        }
        if (tid == 0) g_tick1 = 0u;
    }
}

// ============================ tf32 mma GEMM core =================================
template <int MI>
__device__ __forceinline__ void gemm_mma(const float* __restrict__ A,
                                         const float* __restrict__ W,
                                         float acc[MI][4][4],
                                         int wr, int wc, int g, int t) {
    #pragma unroll
    for (int i = 0; i < MI; i++)
        #pragma unroll
        for (int j = 0; j < 4; j++)
            #pragma unroll
            for (int r = 0; r < 4; r++) acc[i][j][r] = 0.f;
    #pragma unroll 4
    for (int kk = 0; kk < 16; kk++) {
        const int k0 = kk * 8;
        unsigned int a[MI][4];
        #pragma unroll
        for (int mi = 0; mi < MI; mi++) {
            const float* ap = A + (size_t)(wr * (MI * 16) + mi * 16 + g) * APITCH + k0 + t;
            a[mi][0] = __float_as_uint(ap[0]);
            a[mi][1] = __float_as_uint(ap[8 * APITCH]);
            a[mi][2] = __float_as_uint(ap[4]);
            a[mi][3] = __float_as_uint(ap[8 * APITCH + 4]);
        }
        #pragma unroll
        for (int ni = 0; ni < 4; ni++) {
            const float* bp = W + (size_t)(k0 + t) * WPITCH + wc * 32 + ni * 8 + g;
            unsigned int b0 = __float_as_uint(bp[0]);
            unsigned int b1 = __float_as_uint(bp[4 * WPITCH]);
            #pragma unroll
            for (int mi = 0; mi < MI; mi++) {
                asm volatile(
                    "mma.sync.aligned.m16n8k8.row.col.f32.tf32.tf32.f32 "
                    "{%0,%1,%2,%3}, {%4,%5,%6,%7}, {%8,%9}, {%0,%1,%2,%3};\n"
                    : "+f"(acc[mi][ni][0]), "+f"(acc[mi][ni][1]),
                      "+f"(acc[mi][ni][2]), "+f"(acc[mi][ni][3])
                    : "r"(a[mi][0]), "r"(a[mi][1]), "r"(a[mi][2]), "r"(a[mi][3]),
                      "r"(b0), "r"(b1));
            }
        }
    }
}

// ============== q,kf,v = normalize(t) @ {W_phi,W_psi,W_alpha} (mma tf32) =========
__global__ __launch_bounds__(512) void qkv_kernel(const float* __restrict__ g1v,
                                                  const float* __restrict__ be1,
                                                  const float* __restrict__ Wphi,
                                                  const float* __restrict__ Wpsi,
                                                  const float* __restrict__ Walpha) {
    extern __shared__ float sm[];
    float* BufA = sm;                    // [128][APITCH]
    float* BufW = BufA + 128 * APITCH;   // [128][WPITCH]
    __shared__ float sScale[128], sShift[128];
    int tid = threadIdx.x;
    if (tid < 128) {
        float m = g_stats[tid], is = g_stats[128 + tid];
        float sc = is * g1v[tid];
        sScale[tid] = sc;
        sShift[tid] = be1[tid] - m * sc;
    }
    __syncthreads();
    int row0 = blockIdx.x * 128;
    for (int e = tid; e < 4096; e += 512) {
        int r = e >> 5, s = (e & 31) * 4;
        float4 v = *(const float4*)&g_t[(size_t)(row0 + r) * 128 + s];
        float4 o;
        o.x = to_tf32(v.x * sScale[s] + sShift[s]);
        o.y = to_tf32(v.y * sScale[s + 1] + sShift[s + 1]);
        o.z = to_tf32(v.z * sScale[s + 2] + sShift[s + 2]);
        o.w = to_tf32(v.w * sScale[s + 3] + sShift[s + 3]);
        *(float4*)&BufA[r * APITCH + s] = o;
    }

    int wid = tid >> 5, lane = tid & 31;
    int wr = wid >> 2, wc = wid & 3;
    int g = lane >> 2, t = lane & 3;

    #pragma unroll 1
    for (int widx = 0; widx < 3; widx++) {
        const float* W = (widx == 0) ? Wphi : (widx == 1) ? Wpsi : Walpha;
        float* out = (widx == 0) ? g_q : (widx == 1) ? g_kf : g_v;
        for (int e = tid; e < 4096; e += 512) {
            int k = e >> 5, s = (e & 31) * 4;
            float4 v = *(const float4*)&W[(size_t)k * 128 + s];
            float4 o = {to_tf32(v.x), to_tf32(v.y), to_tf32(v.z), to_tf32(v.w)};
            *(float4*)&BufW[k * WPITCH + s] = o;
        }
        __syncthreads();

        float acc[2][4][4];
        gemm_mma<2>(BufA, BufW, acc, wr, wc, g, t);

        #pragma unroll
        for (int mi = 0; mi < 2; mi++) {
            int r0 = row0 + wr * 32 + mi * 16 + g;
            #pragma unroll
            for (int ni = 0; ni < 4; ni++) {
                int c0 = wc * 32 + ni * 8 + 2 * t;
                *(float2*)&out[(size_t)r0 * 128 + c0] =
                    make_float2(acc[mi][ni][0], acc[mi][ni][1]);
                *(float2*)&out[(size_t)(r0 + 8) * 128 + c0] =
                    make_float2(acc[mi][ni][2], acc[mi][ni][3]);
            }
        }
        __syncthreads();
    }
}

// ============================ fused per-point attention (mma tf32) ==============
// 8 points/block, 512 threads. cp.async double-buffered tf32 weights from g_wtf;
// kf/v gathers prefetched into registers; delta in regs; shuffle softmax.
__device__ __forceinline__ void ldW_async(float* dstBase, const float* src, int tid) {
    for (int e = tid; e < 4096; e += 512) {
        int r = e >> 5, c = (e & 31) * 4;
        cp16(dstBase + r * WPITCH + c, src + r * 128 + c);
    }
}

__global__ __launch_bounds__(512) void fused_kernel(const int* __restrict__ coords,
                                                    const float* __restrict__ Wd1,
                                                    const float* __restrict__ bd1,
                                                    const float* __restrict__ bd2,
                                                    const float* __restrict__ bg1,
                                                    const float* __restrict__ bg2) {
    extern __shared__ float sm[];
    float* BufA = sm;                      // [128][APITCH]
    float* W0   = BufA + 128 * APITCH;     // [128][WPITCH]
    float* W1   = W0 + 128 * WPITCH;       // [128][WPITCH]
    float* sQ   = W1 + 128 * WPITCH;       // [8][128]
    float* sRel = sQ + 8 * 128;            // [128][3]
    float* sWd1 = sRel + 128 * 3;          // [3][128]
    float* sBd1 = sWd1 + 384;              // [128]
    int*   sIdx = (int*)(sBd1 + 128);      // [128]

    int tid = threadIdx.x;
    int p0 = blockIdx.x * 8;
    int wid = tid >> 5, lane = tid & 31;
    int wr = wid >> 2, wc = wid & 3;
    int g = lane >> 2, t = lane & 3;

    // async weight loads: group1 = Wd2 -> W0, group2 = Wg1 -> W1
    ldW_async(W0, g_wtf, tid);           cp_commit();
    ldW_async(W1, g_wtf + 16384, tid);   cp_commit();

    if (tid < 128) {
        sIdx[tid] = g_idx[(size_t)p0 * KNN + tid];
        sBd1[tid] = bd1[tid];
    }
    if (tid < 384) sWd1[tid] = Wd1[tid];
    if (tid < 256) {
        int pp = tid >> 5, s = (tid & 31) * 4;
        *(float4*)&sQ[pp * 128 + s] = *(const float4*)&g_q[(size_t)(p0 + pp) * 128 + s];
    }
    __syncthreads();

    // per-thread row indices (used in epilogues)
    int r0_[2], r1_[2], gi0_[2], gi1_[2];
    #pragma unroll
    for (int mi = 0; mi < 2; mi++) {
        r0_[mi] = wr * 32 + mi * 16 + g;
        r1_[mi] = r0_[mi] + 8;
        gi0_[mi] = sIdx[r0_[mi]];
        gi1_[mi] = sIdx[r1_[mi]];
    }
    // prefetch kf gathers (consumed in epilogue1)
    float2 kf0[2][4], kf1[2][4];
    #pragma unroll
    for (int mi = 0; mi < 2; mi++)
        #pragma unroll
        for (int ni = 0; ni < 4; ni++) {
            int c0 = wc * 32 + ni * 8 + 2 * t;
            kf0[mi][ni] = *(const float2*)&g_kf[(size_t)gi0_[mi] * 128 + c0];
            kf1[mi][ni] = *(const float2*)&g_kf[(size_t)gi1_[mi] * 128 + c0];
        }

    if (tid < 128) {
        int i = p0 + (tid >> 4);
        int j = sIdx[tid];
        int4 ci = *(const int4*)&coords[(size_t)i * 4];
        int4 cj = *(const int4*)&coords[(size_t)j * 4];
        sRel[tid * 3 + 0] = (float)(ci.y - cj.y);
        sRel[tid * 3 + 1] = (float)(ci.z - cj.z);
        sRel[tid * 3 + 2] = (float)(ci.w - cj.w);
    }
    __syncthreads();

    // stage 1: BufA <- tf32(relu(rel @ Wd1 + bd1))
    for (int e = tid; e < 128 * 128; e += 512) {
        int r = e >> 7, c = e & 127;
        float v = sBd1[c] + sRel[r * 3] * sWd1[c] + sRel[r * 3 + 1] * sWd1[128 + c]
                + sRel[r * 3 + 2] * sWd1[256 + c];
        BufA[r * APITCH + c] = to_tf32(fmaxf(v, 0.f));
    }
    cp_wait<1>();          // Wd2 resident
    __syncthreads();

    // GEMM1: delta = h1 @ Wd2 + bd2  (registers)
    float dlt[2][4][4];
    gemm_mma<2>(BufA, W0, dlt, wr, wc, g, t);
    #pragma unroll
    for (int mi = 0; mi < 2; mi++)
        #pragma unroll
        for (int ni = 0; ni < 4; ni++) {
            int c0 = wc * 32 + ni * 8 + 2 * t;
            float b0 = __ldg(&bd2[c0]), b1 = __ldg(&bd2[c0 + 1]);
            dlt[mi][ni][0] += b0; dlt[mi][ni][1] += b1;
            dlt[mi][ni][2] += b0; dlt[mi][ni][3] += b1;
        }
    __syncthreads();       // all GEMM1 reads of BufA/W0 complete

    // group3: Wg2 -> W0 (W0 now free)
    ldW_async(W0, g_wtf + 32768, tid);
    cp_commit();

    // epilogue1: BufA <- tf32(q - kf + delta)
    #pragma unroll
    for (int mi = 0; mi < 2; mi++) {
        int pl = wr * 2 + mi;
        #pragma unroll
        for (int ni = 0; ni < 4; ni++) {
            int c0 = wc * 32 + ni * 8 + 2 * t;
            float q0 = sQ[pl * 128 + c0], q1 = sQ[pl * 128 + c0 + 1];
            *(float2*)&BufA[r0_[mi] * APITCH + c0] =
                make_float2(to_tf32(q0 - kf0[mi][ni].x + dlt[mi][ni][0]),
                            to_tf32(q1 - kf0[mi][ni].y + dlt[mi][ni][1]));
            *(float2*)&BufA[r1_[mi] * APITCH + c0] =
                make_float2(to_tf32(q0 - kf1[mi][ni].x + dlt[mi][ni][2]),
                            to_tf32(q1 - kf1[mi][ni].y + dlt[mi][ni][3]));
        }
    }
    cp_wait<1>();          // Wg1 resident
    __syncthreads();

    // GEMM2: h2 = relu(apre @ Wg1 + bg1)
    float acc2[2][4][4];
    gemm_mma<2>(BufA, W1, acc2, wr, wc, g, t);
    __syncthreads();       // GEMM2 reads of BufA complete
    #pragma unroll
    for (int mi = 0; mi < 2; mi++) {
        #pragma unroll
        for (int ni = 0; ni < 4; ni++) {
            int c0 = wc * 32 + ni * 8 + 2 * t;
            float b0 = __ldg(&bg1[c0]), b1 = __ldg(&bg1[c0 + 1]);
            *(float2*)&BufA[r0_[mi] * APITCH + c0] =
                make_float2(to_tf32(fmaxf(acc2[mi][ni][0] + b0, 0.f)),
                            to_tf32(fmaxf(acc2[mi][ni][1] + b1, 0.f)));
            *(float2*)&BufA[r1_[mi] * APITCH + c0] =
                make_float2(to_tf32(fmaxf(acc2[mi][ni][2] + b0, 0.f)),
                            to_tf32(fmaxf(acc2[mi][ni][3] + b1, 0.f)));
        }
    }
    // prefetch v gathers (consumed in softmax)
    float2 v0r[2][4], v1r[2][4];
    #pragma unroll
    for (int mi = 0; mi < 2; mi++)
        #pragma unroll
        for (int ni = 0; ni < 4; ni++) {
            int c0 = wc * 32 + ni * 8 + 2 * t;
            v0r[mi][ni] = *(const float2*)&g_v[(size_t)gi0_[mi] * 128 + c0];
            v1r[mi][ni] = *(const float2*)&g_v[(size_t)gi1_[mi] * 128 + c0];
        }
    cp_wait<0>();          // Wg2 resident
    __syncthreads();

    // GEMM3: logits = h2 @ Wg2 (+bg2 below)
    gemm_mma<2>(BufA, W0, acc2, wr, wc, g, t);

    // softmax over K + aggregate, in registers/shuffles
    #pragma unroll
    for (int mi = 0; mi < 2; mi++) {
        int pl = wr * 2 + mi;
        #pragma unroll
        for (int ni = 0; ni < 4; ni++) {
            int c0 = wc * 32 + ni * 8 + 2 * t;
            float b0 = __ldg(&bg2[c0]), b1 = __ldg(&bg2[c0 + 1]);
            float l00 = acc2[mi][ni][0] + b0, l01 = acc2[mi][ni][1] + b1;
            float l10 = acc2[mi][ni][2] + b0, l11 = acc2[mi][ni][3] + b1;
            float w00 = v0r[mi][ni].x + dlt[mi][ni][0], w01 = v0r[mi][ni].y + dlt[mi][ni][1];
            float w10 = v1r[mi][ni].x + dlt[mi][ni][2], w11 = v1r[mi][ni].y + dlt[mi][ni][3];

            float m0 = fmaxf(l00, l10);
            m0 = fmaxf(m0, __shfl_xor_sync(0xffffffffu, m0, 4));
            m0 = fmaxf(m0, __shfl_xor_sync(0xffffffffu, m0, 8));
            m0 = fmaxf(m0, __shfl_xor_sync(0xffffffffu, m0, 16));
            float m1 = fmaxf(l01, l11);
            m1 = fmaxf(m1, __shfl_xor_sync(0xffffffffu, m1, 4));
            m1 = fmaxf(m1, __shfl_xor_sync(0xffffffffu, m1, 8));
            m1 = fmaxf(m1, __shfl_xor_sync(0xffffffffu, m1, 16));

            float e00 = __expf(l00 - m0), e10 = __expf(l10 - m0);
            float e01 = __expf(l01 - m1), e11 = __expf(l11 - m1);
            float s0 = e00 + e10, s1 = e01 + e11;
            float a0 = e00 * w00 + e10 * w10;
            float a1 = e01 * w01 + e11 * w11;
            s0 += __shfl_xor_sync(0xffffffffu, s0, 4);
            s0 += __shfl_xor_sync(0xffffffffu, s0, 8);
            s0 += __shfl_xor_sync(0xffffffffu, s0, 16);
            s1 += __shfl_xor_sync(0xffffffffu, s1, 4);
            s1 += __shfl_xor_sync(0xffffffffu, s1, 8);
            s1 += __shfl_xor_sync(0xffffffffu, s1, 16);
            a0 += __shfl_xor_sync(0xffffffffu, a0, 4);
            a0 += __shfl_xor_sync(0xffffffffu, a0, 8);
            a0 += __shfl_xor_sync(0xffffffffu, a0, 16);
            a1 += __shfl_xor_sync(0xffffffffu, a1, 4);
            a1 += __shfl_xor_sync(0xffffffffu, a1, 8);
            a1 += __shfl_xor_sync(0xffffffffu, a1, 16);

            if (g == 0)
                *(float2*)&g_agg[(size_t)(p0 + pl) * 128 + c0] =
                    make_float2(a0 / s0, a1 / s1);
        }
    }
}

// ========== down-proj: out = agg @ W_down + b_down, fused BN partials ===========
__global__ __launch_bounds__(256) void down_kernel(const float* __restrict__ W,
                                                   const float* __restrict__ bias,
                                                   float* __restrict__ out) {
    __shared__ float As[16][128];
    __shared__ float Bs[16][64];
    __shared__ float redS[16][64];
    __shared__ float redSS[16][64];
    __shared__ bool  sLast;
    int tid = threadIdx.x;
    int ty = tid >> 4, tx = tid & 15;
    int row0 = blockIdx.x * 128;
    float acc[8][4] = {};
    for (int kt = 0; kt < 128; kt += 16) {
        for (int e = tid; e < 512; e += 256) {
            int r = e >> 2, s = e & 3;
            float4 v = *(const float4*)&g_agg[(size_t)(row0 + r) * 128 + kt + s * 4];
            As[s * 4 + 0][r] = v.x; As[s * 4 + 1][r] = v.y;
            As[s * 4 + 2][r] = v.z; As[s * 4 + 3][r] = v.w;
        }
        if (tid < 256) {
            int k = tid >> 4, s = tid & 15;
            *(float4*)&Bs[k][s * 4] = *(const float4*)&W[(size_t)(kt + k) * 64 + s * 4];
        }
        __syncthreads();
        #pragma unroll
        for (int k = 0; k < 16; k++) {
            float4 a0 = *(const float4*)&As[k][ty * 8];
            float4 a1 = *(const float4*)&As[k][ty * 8 + 4];
            float4 b = *(const float4*)&Bs[k][tx * 4];
            float av[8] = {a0.x, a0.y, a0.z, a0.w, a1.x, a1.y, a1.z, a1.w};
            float bv[4] = {b.x, b.y, b.z, b.w};
            #pragma unroll
            for (int i = 0; i < 8; i++)
                #pragma unroll
                for (int j = 0; j < 4; j++)
                    acc[i][j] += av[i] * bv[j];
        }
        __syncthreads();
    }
    #pragma unroll
    for (int j = 0; j < 4; j++) {
        float b = __ldg(&bias[tx * 4 + j]);
        float s = 0.f, ss = 0.f;
        #pragma unroll
        for (int i = 0; i < 8; i++) {
            float v = acc[i][j] + b;
            out[(size_t)(row0 + ty * 8 + i) * 64 + tx * 4 + j] = v;
            s += v; ss += v * v;
        }
        redS[ty][tx * 4 + j] = s;
        redSS[ty][tx * 4 + j] = ss;
    }
    __syncthreads();
    if (tid < 64) {
        float s = 0.f, ss = 0.f;
        #pragma unroll
        for (int u = 0; u < 16; u++) { s += redS[u][tid]; ss += redSS[u][tid]; }
        g_part[blockIdx.x * 128 + tid]      = s;
        g_part[blockIdx.x * 128 + 64 + tid] = ss;
    }
    __threadfence();
    __syncthreads();
    if (tid == 0)
        sLast = (atomicAdd(&g_tick2, 1u) == gridDim.x - 1);
    __syncthreads();
    if (sLast) {
        int c = tid & 63, sub = tid >> 6;    // 4 subs x 64 channels
        float s = 0.f, ss = 0.f;
        for (int b = sub; b < 128; b += 4) {
            s  += g_part[b * 128 + c];
            ss += g_part[b * 128 + 64 + c];
        }
        redS[sub][c] = s; redSS[sub][c] = ss;
        __syncthreads();
        if (tid < 64) {
            float S = redS[0][tid] + redS[1][tid] + redS[2][tid] + redS[3][tid];
            float SS = redSS[0][tid] + redSS[1][tid] + redSS[2][tid] + redSS[3][tid];
            float m = S / (float)TOT;
            float var = SS / (float)TOT - m * m;
            g_stats[tid]      = m;
            g_stats[64 + tid] = rsqrtf(var + 1e-5f);
        }
        if (tid == 0) g_tick2 = 0u;
    }
}

// ============================ final BN + residual ================================
__global__ __launch_bounds__(256) void final_kernel(const float* __restrict__ x,
                                                    const float* __restrict__ g2,
                                                    const float* __restrict__ be2,
                                                    float* __restrict__ out) {
    int e = blockIdx.x * 256 + threadIdx.x;
    if (e < TOT * IND) {
        int c = e & 63;
        float m = g_stats[c], is = g_stats[IND + c];
        out[e] = (out[e] - m) * is * g2[c] + be2[c] + x[e];
    }
}

// ============================ launch =============================================
extern "C" void kernel_launch(void* const* d_in, const int* in_sizes, int n_in,
                              void* d_out, int out_size) {
    const int*   coords  = (const int*)  d_in[0];
    const float* x       = (const float*)d_in[1];
    const float* W_top   = (const float*)d_in[2];
    const float* b_top   = (const float*)d_in[3];
    const float* g1      = (const float*)d_in[4];
    const float* be1     = (const float*)d_in[5];
    const float* W_phi   = (const float*)d_in[6];
    const float* W_psi   = (const float*)d_in[7];
    const float* W_alpha = (const float*)d_in[8];
    const float* Wd1     = (const float*)d_in[9];
    const float* bd1     = (const float*)d_in[10];
    const float* Wd2     = (const float*)d_in[11];
    const float* bd2     = (const float*)d_in[12];
    const float* Wg1     = (const float*)d_in[13];
    const float* bg1     = (const float*)d_in[14];
    const float* Wg2     = (const float*)d_in[15];
    const float* bg2     = (const float*)d_in[16];
    const float* W_down  = (const float*)d_in[17];
    const float* b_down  = (const float*)d_in[18];
    const float* g2      = (const float*)d_in[19];
    const float* be2     = (const float*)d_in[20];
    float* out = (float*)d_out;

    const size_t SMEM_F = (size_t)(128 * APITCH + 2 * 128 * WPITCH + 8 * 128
                                   + 128 * 3 + 384 + 128 + 128) * 4;
    const size_t SMEM_Q = (size_t)(128 * APITCH + 128 * WPITCH) * 4;
    cudaFuncSetAttribute(fused_kernel, cudaFuncAttributeMaxDynamicSharedMemorySize,
                         (int)SMEM_F);
    cudaFuncSetAttribute(qkv_kernel, cudaFuncAttributeMaxDynamicSharedMemorySize,
                         (int)SMEM_Q);

    conv_kernel<<<96, 512>>>(Wd2, Wg1, Wg2);
    ball_kernel<<<TOT / 128, 128>>>(coords);
    topproj_kernel<<<TOT / 128, 256>>>(x, W_top, b_top);
    qkv_kernel<<<TOT / 128, 512, SMEM_Q>>>(g1, be1, W_phi, W_psi, W_alpha);
    fused_kernel<<<TOT / 8, 512, SMEM_F>>>(coords, Wd1, bd1, bd2, bg1, bg2);
    down_kernel<<<TOT / 128, 256>>>(W_down, b_down, out);
    final_kernel<<<(TOT * IND + 255) / 256, 256>>>(x, g2, be2, out);
}